// round 14
// baseline (speedup 1.0000x reference)
#include <cuda_runtime.h>
#include <cuda_bf16.h>
#include <math.h>

// ---------------- problem constants ----------------
#define BATCH 64
#define HDIM  2048
#define SEQ   2048
#define NH    32
#define NKV   4
#define GQA   8
#define HD    128
#define NEXP  32
#define IDIM  768
#define TOPK  4
#define QKV_N 5120
#define EPS   1e-6f
#define SCHUNK 256
#define NCHUNK (SEQ / SCHUNK)

// attention dynamic smem layout
#define SK_STRIDE 136
#define ASM_SQ  (256 * SK_STRIDE * 2)                 // 69632: after sK bf16[256][136]
#define ASM_SC  (ASM_SQ + 8 * HD * 4)                 // 73728: after sQ f32[8][128]
#define ASM_TOT (ASM_SC + 256 * 8 * 4)                // 81920

// ---------------- scratch (device globals) ----------------
// args must come from cudaGetSymbolAddress (ATS host-shadow bug, rounds 1-5).
__device__ float g_hn   [BATCH * HDIM];
__device__ float g_qkv  [BATCH * QKV_N];
__device__ float g_hs2  [BATCH * HDIM];
__device__ float g_h2   [BATCH * HDIM];
__device__ float g_ypair[BATCH * TOPK * HDIM];
__device__ float g_part [4 * BATCH * QKV_N];
__device__ int   g_cnt  [NEXP];
__device__ int   g_tok  [NEXP * BATCH];
__device__ int   g_slot [NEXP * BATCH];
__device__ float g_wt   [NEXP * BATCH];
__device__ float g_pm [BATCH * NKV * NCHUNK * GQA];
__device__ float g_pl [BATCH * NKV * NCHUNK * GQA];
__device__ float g_po [BATCH * NKV * NCHUNK * GQA * HD];
// bf16 split activations
__device__ __nv_bfloat16 g_hnh [BATCH * HDIM];
__device__ __nv_bfloat16 g_hnl [BATCH * HDIM];
__device__ __nv_bfloat16 g_ath [BATCH * NH * HD];
__device__ __nv_bfloat16 g_atl [BATCH * NH * HD];
__device__ __nv_bfloat16 g_h2h [BATCH * HDIM];
__device__ __nv_bfloat16 g_h2l [BATCH * HDIM];
__device__ __nv_bfloat16 g_acth[NEXP * BATCH * IDIM];
__device__ __nv_bfloat16 g_actl[NEXP * BATCH * IDIM];

// ---------------- helpers ----------------
__device__ __forceinline__ void split1(float f, __nv_bfloat16& h, __nv_bfloat16& l) {
    h = __float2bfloat16(f);
    l = __float2bfloat16(f - __bfloat162float(h));
}
__device__ __forceinline__ unsigned pk2(__nv_bfloat16 a, __nv_bfloat16 b) {
    __nv_bfloat162 h; h.x = a; h.y = b;
    return *reinterpret_cast<unsigned*>(&h);
}
__device__ __forceinline__ void mma16816(
    float& c0, float& c1, float& c2, float& c3,
    unsigned a0, unsigned a1, unsigned a2, unsigned a3,
    unsigned b0, unsigned b1)
{
    asm volatile(
        "mma.sync.aligned.m16n8k16.row.col.f32.bf16.bf16.f32 "
        "{%0,%1,%2,%3},{%4,%5,%6,%7},{%8,%9},{%0,%1,%2,%3};"
        : "+f"(c0), "+f"(c1), "+f"(c2), "+f"(c3)
        : "r"(a0), "r"(a1), "r"(a2), "r"(a3), "r"(b0), "r"(b1));
}

// ---------------- reset ----------------
__global__ void reset_k() {
    if (threadIdx.x < NEXP) g_cnt[threadIdx.x] = 0;
}

// ---------------- RMSNorm: fp32 + bf16 split out ----------------
__global__ __launch_bounds__(256) void rmsnorm_k(
    const float* __restrict__ x, const float* __restrict__ w,
    float* __restrict__ y, __nv_bfloat16* __restrict__ yh, __nv_bfloat16* __restrict__ yl)
{
    int b = blockIdx.x, tid = threadIdx.x;
    const float* xb = x + b * HDIM;
    float s = 0.f;
    for (int i = tid; i < HDIM; i += 256) { float v = xb[i]; s += v * v; }
    for (int o = 16; o; o >>= 1) s += __shfl_xor_sync(0xffffffffu, s, o);
    __shared__ float red[8];
    __shared__ float inv;
    if ((tid & 31) == 0) red[tid >> 5] = s;
    __syncthreads();
    if (tid == 0) {
        float t = 0.f;
        #pragma unroll
        for (int i = 0; i < 8; i++) t += red[i];
        inv = rsqrtf(t * (1.f / HDIM) + EPS);
    }
    __syncthreads();
    float iv = inv;
    for (int i = tid; i < HDIM; i += 256) {
        float v = xb[i] * iv * w[i];
        y[b * HDIM + i] = v;
        __nv_bfloat16 h, l; split1(v, h, l);
        yh[b * HDIM + i] = h; yl[b * HDIM + i] = l;
    }
}

// ---------------- tensor GEMM partial (bf16x3) ----------------
__global__ __launch_bounds__(256) void gemm_part_tc(
    const __nv_bfloat16* __restrict__ Ah, const __nv_bfloat16* __restrict__ Al,
    const float* __restrict__ W, float* __restrict__ part, int N, int K, int ksplit)
{
    __shared__ __nv_bfloat16 sAh[2][64][40], sAl[2][64][40];
    __shared__ __nv_bfloat16 sWh[2][64][40], sWl[2][64][40];
    int nb = blockIdx.x * 64;
    int ks = blockIdx.y;
    int klen = K / ksplit, kbeg = ks * klen, tiles = klen / 32;
    int tid = threadIdx.x, lane = tid & 31, warp = tid >> 5;
    int mw = warp & 3, nw = warp >> 2;
    int gr = lane >> 2, tc = lane & 3;

    int lm = tid >> 2, lk8 = (tid & 3) * 8;
    const __nv_bfloat16* Agh = Ah + (long)lm * K + kbeg + lk8;
    const __nv_bfloat16* Agl = Al + (long)lm * K + kbeg + lk8;
    const float* Wg = W + (long)(nb + lm) * K + kbeg + lk8;

    float acc[4][4] = {};
    uint4 rah[2], ral[2];
    float4 rw[2][2];
    #pragma unroll
    for (int s = 0; s < 2; s++) {
        rah[s] = *(const uint4*)(Agh + s * 32);
        ral[s] = *(const uint4*)(Agl + s * 32);
        rw[s][0] = *(const float4*)(Wg + s * 32);
        rw[s][1] = *(const float4*)(Wg + s * 32 + 4);
    }

    for (int t = 0; t < tiles; t += 2) {
        #pragma unroll
        for (int p = 0; p < 2; p++) {
            *(uint4*)&sAh[p][lm][lk8] = rah[p];
            *(uint4*)&sAl[p][lm][lk8] = ral[p];
            {
                float f[8] = {rw[p][0].x, rw[p][0].y, rw[p][0].z, rw[p][0].w,
                              rw[p][1].x, rw[p][1].y, rw[p][1].z, rw[p][1].w};
                __nv_bfloat16 h[8], l[8];
                #pragma unroll
                for (int i = 0; i < 8; i++) split1(f[i], h[i], l[i]);
                uint4 uh = make_uint4(pk2(h[0],h[1]), pk2(h[2],h[3]), pk2(h[4],h[5]), pk2(h[6],h[7]));
                uint4 ul = make_uint4(pk2(l[0],l[1]), pk2(l[2],l[3]), pk2(l[4],l[5]), pk2(l[6],l[7]));
                *(uint4*)&sWh[p][lm][lk8] = uh;
                *(uint4*)&sWl[p][lm][lk8] = ul;
            }
            if (t + p + 2 < tiles) {
                rah[p] = *(const uint4*)(Agh + (t + p + 2) * 32);
                ral[p] = *(const uint4*)(Agl + (t + p + 2) * 32);
                rw[p][0] = *(const float4*)(Wg + (t + p + 2) * 32);
                rw[p][1] = *(const float4*)(Wg + (t + p + 2) * 32 + 4);
            }
            __syncthreads();
            #pragma unroll
            for (int k16 = 0; k16 < 2; k16++) {
                int kc = k16 * 16 + tc * 2;
                int ra = mw * 16 + gr;
                unsigned ah0 = *(const unsigned*)&sAh[p][ra][kc];
                unsigned ah1 = *(const unsigned*)&sAh[p][ra + 8][kc];
                unsigned ah2 = *(const unsigned*)&sAh[p][ra][kc + 8];
                unsigned ah3 = *(const unsigned*)&sAh[p][ra + 8][kc + 8];
                unsigned al0 = *(const unsigned*)&sAl[p][ra][kc];
                unsigned al1 = *(const unsigned*)&sAl[p][ra + 8][kc];
                unsigned al2 = *(const unsigned*)&sAl[p][ra][kc + 8];
                unsigned al3 = *(const unsigned*)&sAl[p][ra + 8][kc + 8];
                #pragma unroll
                for (int j = 0; j < 4; j++) {
                    int n = nw * 32 + j * 8 + gr;
                    unsigned bh0 = *(const unsigned*)&sWh[p][n][kc];
                    unsigned bh1 = *(const unsigned*)&sWh[p][n][kc + 8];
                    unsigned bl0 = *(const unsigned*)&sWl[p][n][kc];
                    unsigned bl1 = *(const unsigned*)&sWl[p][n][kc + 8];
                    mma16816(acc[j][0], acc[j][1], acc[j][2], acc[j][3],
                             ah0, ah1, ah2, ah3, bh0, bh1);
                    mma16816(acc[j][0], acc[j][1], acc[j][2], acc[j][3],
                             ah0, ah1, ah2, ah3, bl0, bl1);
                    mma16816(acc[j][0], acc[j][1], acc[j][2], acc[j][3],
                             al0, al1, al2, al3, bh0, bh1);
                }
            }
            __syncthreads();
        }
    }

    #pragma unroll
    for (int j = 0; j < 4; j++) {
        int col = nb + nw * 32 + j * 8 + tc * 2;
        long r0 = (long)(ks * 64 + mw * 16 + gr) * N + col;
        *(float2*)&part[r0] = make_float2(acc[j][0], acc[j][1]);
        *(float2*)&part[r0 + 8L * N] = make_float2(acc[j][2], acc[j][3]);
    }
}

// ---------------- GEMM reduce ----------------
__global__ __launch_bounds__(256) void gemm_reduce_k(
    const float* __restrict__ part, const float* __restrict__ bias,
    const float* __restrict__ res, float* __restrict__ C, int N, int ksplit)
{
    int idx = (blockIdx.x * 256 + threadIdx.x) * 4;
    int m = idx / N, n = idx % N;
    float4 s = bias ? *(const float4*)&bias[n] : make_float4(0.f, 0.f, 0.f, 0.f);
    for (int ks = 0; ks < ksplit; ks++) {
        float4 p = *(const float4*)&part[((long)(ks * 64 + m)) * N + n];
        s.x += p.x; s.y += p.y; s.z += p.z; s.w += p.w;
    }
    if (res) {
        float4 r = *(const float4*)&res[idx];
        s.x += r.x; s.y += r.y; s.z += r.z; s.w += r.w;
    }
    *(float4*)&C[idx] = s;
}

// ---------------- attention: tensor-core QK^T + fp32 online softmax/PV ----------
// grid (NCHUNK, NKV, BATCH), 256 thr, dynamic smem ASM_TOT.
__global__ __launch_bounds__(256) void attn_part_tc(
    const float* __restrict__ kc, const float* __restrict__ vc,
    const int* __restrict__ seq_lens)
{
    extern __shared__ char smem[];
    __nv_bfloat16* sK = (__nv_bfloat16*)smem;        // [256][SK_STRIDE]
    float* sQ = (float*)(smem + ASM_SQ);             // [8][128] (scaled)
    float* sc = (float*)(smem + ASM_SC);             // [256][8]
    // overlay (after phase B; sK region is dead then)
    float* so  = (float*)smem;                       // [8 warps][8 heads][128]
    float* smx = (float*)(smem + 32768);             // [8][8]
    float* sll = (float*)(smem + 33024);             // [8][8]

    int c  = blockIdx.x;
    int kv = blockIdx.y;
    int b  = blockIdx.z;
    int tid = threadIdx.x, warp = tid >> 5, lane = tid & 31;
    int gr = lane >> 2, tc = lane & 3;
    int sl = seq_lens[b];
    if (sl < 0) sl = 0;
    if (sl > SEQ - 1) sl = SEQ - 1;
    int L  = sl + 1;
    int s0 = c * SCHUNK;
    if (s0 >= L) return;
    int s1 = s0 + SCHUNK; if (s1 > L) s1 = L;
    const float scale = 0.08838834764831845f;

    const float* qbase = g_qkv + b * QKV_N + kv * GQA * HD;
    const float* knew  = g_qkv + b * QKV_N + NH * HD + kv * HD;
    const float* vnew  = g_qkv + b * QKV_N + (NH + NKV) * HD + kv * HD;

    // stage Q (scaled) into sQ
    {
        float4 qv = *(const float4*)(qbase + tid * 4);
        qv.x *= scale; qv.y *= scale; qv.z *= scale; qv.w *= scale;
        *(float4*)&sQ[tid * 4] = qv;
    }
    // stage K chunk -> bf16 smem
    #pragma unroll 4
    for (int it = 0; it < 32; it++) {
        int idx = it * 256 + tid;
        int pos = idx >> 5, q4 = idx & 31;
        int sg = s0 + pos;
        const float* src = (sg == sl) ? (knew + q4 * 4)
                          : (kc + ((size_t)(b * SEQ + sg) * NKV + kv) * HD + q4 * 4);
        float4 kf = *(const float4*)src;
        uint2 pk = make_uint2(
            pk2(__float2bfloat16(kf.x), __float2bfloat16(kf.y)),
            pk2(__float2bfloat16(kf.z), __float2bfloat16(kf.w)));
        *(uint2*)&sK[pos * SK_STRIDE + q4 * 4] = pk;
    }
    __syncthreads();

    // build Q B-fragments (head = lane>>2, bf16x2 split)
    unsigned bh0[8], bh1[8], bl0[8], bl1[8];
    {
        int qh = gr;                      // head 0..7
        #pragma unroll
        for (int kk = 0; kk < 8; kk++) {
            int kb = kk * 16 + tc * 2;
            float q0 = sQ[qh * HD + kb],     q1 = sQ[qh * HD + kb + 1];
            float q2 = sQ[qh * HD + kb + 8], q3 = sQ[qh * HD + kb + 9];
            __nv_bfloat16 h0,l0,h1,l1,h2,l2,h3,l3;
            split1(q0,h0,l0); split1(q1,h1,l1); split1(q2,h2,l2); split1(q3,h3,l3);
            bh0[kk] = pk2(h0,h1); bl0[kk] = pk2(l0,l1);
            bh1[kk] = pk2(h2,h3); bl1[kk] = pk2(l2,l3);
        }
    }

    // scores: warp handles 2 M-tiles (32 positions)
    #pragma unroll
    for (int mt = 0; mt < 2; mt++) {
        int p0 = (warp * 2 + mt) * 16;
        float c0 = 0.f, c1 = 0.f, c2 = 0.f, c3 = 0.f;
        #pragma unroll
        for (int kk = 0; kk < 8; kk++) {
            const __nv_bfloat16* ab = &sK[(p0 + gr) * SK_STRIDE + kk * 16 + tc * 2];
            unsigned a0 = *(const unsigned*)ab;
            unsigned a1 = *(const unsigned*)(ab + 8 * SK_STRIDE);
            unsigned a2 = *(const unsigned*)(ab + 8);
            unsigned a3 = *(const unsigned*)(ab + 8 * SK_STRIDE + 8);
            mma16816(c0, c1, c2, c3, a0, a1, a2, a3, bh0[kk], bh1[kk]);
            mma16816(c0, c1, c2, c3, a0, a1, a2, a3, bl0[kk], bl1[kk]);
        }
        sc[(p0 + gr) * 8 + tc * 2]     = c0;
        sc[(p0 + gr) * 8 + tc * 2 + 1] = c1;
        sc[(p0 + gr + 8) * 8 + tc * 2]     = c2;
        sc[(p0 + gr + 8) * 8 + tc * 2 + 1] = c3;
    }
    __syncthreads();

    // phase B: fp32 online softmax + V accumulation (scores from smem)
    float m[GQA], l[GQA];
    float4 o[GQA];
    #pragma unroll
    for (int h = 0; h < GQA; h++) {
        m[h] = -INFINITY; l[h] = 0.f; o[h] = make_float4(0.f, 0.f, 0.f, 0.f);
    }
    for (int s = s0 + warp; s < s1; s += 8) {
        const float* vp = (s == sl) ? vnew : (vc + ((size_t)(b * SEQ + s) * NKV + kv) * HD);
        float4 vv = *(const float4*)(vp + lane * 4);
        float4 sA = *(const float4*)&sc[(s - s0) * 8];
        float4 sB = *(const float4*)&sc[(s - s0) * 8 + 4];
        float scs[8] = {sA.x, sA.y, sA.z, sA.w, sB.x, sB.y, sB.z, sB.w};
        #pragma unroll
        for (int h = 0; h < GQA; h++) {
            float sv = scs[h];
            if (sv <= m[h]) {                       // fast path: no rescale
                float p = __expf(sv - m[h]);
                l[h] += p;
                o[h].x = fmaf(p, vv.x, o[h].x);
                o[h].y = fmaf(p, vv.y, o[h].y);
                o[h].z = fmaf(p, vv.z, o[h].z);
                o[h].w = fmaf(p, vv.w, o[h].w);
            } else {                                // new max: p == 1
                float corr = __expf(m[h] - sv);
                l[h] = fmaf(l[h], corr, 1.f);
                o[h].x = fmaf(o[h].x, corr, vv.x);
                o[h].y = fmaf(o[h].y, corr, vv.y);
                o[h].z = fmaf(o[h].z, corr, vv.z);
                o[h].w = fmaf(o[h].w, corr, vv.w);
                m[h] = sv;
            }
        }
    }

    // per-warp partials to overlay region (sK is dead; sc untouched)
    #pragma unroll
    for (int h = 0; h < GQA; h++) {
        if (lane == 0) { smx[warp * 8 + h] = m[h]; sll[warp * 8 + h] = l[h]; }
        *(float4*)&so[((warp * 8 + h) << 7) + lane * 4] = o[h];
    }
    __syncthreads();

    int pbase = ((b * NKV + kv) * NCHUNK + c) * GQA;
    for (int idx = tid; idx < GQA * HD; idx += 256) {
        int h = idx >> 7, d = idx & (HD - 1);
        float M = -INFINITY;
        #pragma unroll
        for (int w = 0; w < 8; w++) M = fmaxf(M, smx[w * 8 + h]);
        float acc = 0.f, Ls = 0.f;
        #pragma unroll
        for (int w = 0; w < 8; w++) {
            float cw = __expf(smx[w * 8 + h] - M);
            acc += cw * so[((w * 8 + h) << 7) + d];
            Ls  += cw * sll[w * 8 + h];
        }
        g_po[(pbase + h) * HD + d] = acc;
        if (d == 0) { g_pm[pbase + h] = M; g_pl[pbase + h] = Ls; }
    }
}

// ---------------- combine split-S partials -> bf16 split ----------------
__global__ __launch_bounds__(256) void attn_comb_k(
    const int* __restrict__ seq_lens,
    __nv_bfloat16* __restrict__ outh, __nv_bfloat16* __restrict__ outl)
{
    int b  = blockIdx.x >> 2;
    int kv = blockIdx.x & 3;
    int tid = threadIdx.x;
    int sl = seq_lens[b];
    if (sl < 0) sl = 0;
    if (sl > SEQ - 1) sl = SEQ - 1;
    int nch = sl / SCHUNK + 1;
    int base = (b * NKV + kv) * NCHUNK;

    for (int idx = tid; idx < GQA * HD; idx += 256) {
        int h = idx >> 7, d = idx & (HD - 1);
        float M = -INFINITY;
        for (int c = 0; c < nch; c++) M = fmaxf(M, g_pm[(base + c) * GQA + h]);
        float acc = 0.f, Ls = 0.f;
        for (int c = 0; c < nch; c++) {
            float w = __expf(g_pm[(base + c) * GQA + h] - M);
            acc += w * g_po[((base + c) * GQA + h) * HD + d];
            Ls  += w * g_pl[(base + c) * GQA + h];
        }
        float v = acc / Ls;
        __nv_bfloat16 hh, ll; split1(v, hh, ll);
        long o = (long)b * NH * HD + (kv * GQA + h) * HD + d;
        outh[o] = hh; outl[o] = ll;
    }
}

// ---------------- gate ----------------
__global__ __launch_bounds__(256) void gate_k(const float* __restrict__ gw)
{
    int b = blockIdx.x, tid = threadIdx.x, warp = tid >> 5, lane = tid & 31;
    __shared__ float lg[NEXP];
    const float* h = g_h2 + b * HDIM;
    for (int e = warp; e < NEXP; e += 8) {
        const float* g = gw + e * HDIM;
        float s = 0.f;
        for (int i = lane; i < HDIM; i += 32) s += h[i] * g[i];
        for (int o = 16; o; o >>= 1) s += __shfl_xor_sync(0xffffffffu, s, o);
        if (lane == 0) lg[e] = s;
    }
    __syncthreads();
    if (tid == 0) {
        float val[TOPK]; int idx[TOPK];
        unsigned used = 0;
        for (int j = 0; j < TOPK; j++) {
            float best = -1e30f; int bi = 0;
            for (int e = 0; e < NEXP; e++)
                if (!((used >> e) & 1u) && lg[e] > best) { best = lg[e]; bi = e; }
            used |= 1u << bi; val[j] = best; idx[j] = bi;
        }
        float s = 0.f, wj[TOPK];
        for (int j = 0; j < TOPK; j++) { wj[j] = expf(val[j] - val[0]); s += wj[j]; }
        float is = 1.f / s;
        for (int j = 0; j < TOPK; j++) {
            int e = idx[j];
            int pos = atomicAdd(&g_cnt[e], 1);
            g_tok [e * BATCH + pos] = b;
            g_slot[e * BATCH + pos] = j;
            g_wt  [e * BATCH + pos] = wj[j] * is;
        }
    }
}

// ---------------- MoE w1 (tensor, bf16x3, fused SwiGLU) ----------------
__global__ __launch_bounds__(256) void moe_w1_tc(const float* __restrict__ w1)
{
    int e = blockIdx.y;
    int cnt = g_cnt[e];
    int m0 = blockIdx.z * 16;
    if (m0 >= cnt) return;
    int ib = blockIdx.x * 64;

    __shared__ __align__(16) char SM[46080];
    __nv_bfloat16* pAh = (__nv_bfloat16*)SM;
    __nv_bfloat16* pAl = pAh + 1280;
    __nv_bfloat16* pWh = pAl + 1280;
    __nv_bfloat16* pWl = pWh + 10240;
    float* Csm = (float*)SM;
    __shared__ int toks[16];

    int tid = threadIdx.x, lane = tid & 31, warp = tid >> 5;
    int gr = lane >> 2, tc = lane & 3;
    if (tid < 16) toks[tid] = (m0 + tid < cnt) ? g_tok[e * BATCH + m0 + tid]
                                               : g_tok[e * BATCH];
    __syncthreads();

    int ar = tid >> 4, akp = (tid & 15) * 2;
    const __nv_bfloat16* Agh = g_h2h + (long)toks[ar] * HDIM + akp;
    const __nv_bfloat16* Agl = g_h2l + (long)toks[ar] * HDIM + akp;
    int lw = tid >> 1, wk = (tid & 1) * 16;
    long wrow = (long)e * 2 * IDIM + ((lw < 64) ? (ib + lw) : (IDIM + ib + lw - 64));
    const float* Wg = w1 + wrow * HDIM + wk;

    const int tiles = HDIM / 32;
    float acc[2][4] = {};

    unsigned rah[2], ral[2];
    float4 rw[2][4];
    #pragma unroll
    for (int s = 0; s < 2; s++) {
        rah[s] = *(const unsigned*)(Agh + s * 32);
        ral[s] = *(const unsigned*)(Agl + s * 32);
        #pragma unroll
        for (int q = 0; q < 4; q++) rw[s][q] = *(const float4*)(Wg + s * 32 + q * 4);
    }

    for (int t = 0; t < tiles; t += 2) {
        #pragma unroll
        for (int p = 0; p < 2; p++) {
            *(unsigned*)&pAh[p * 640 + ar * 40 + akp] = rah[p];
            *(unsigned*)&pAl[p * 640 + ar * 40 + akp] = ral[p];
            {
                float f[16];
                #pragma unroll
                for (int q = 0; q < 4; q++) {
                    f[q*4+0] = rw[p][q].x; f[q*4+1] = rw[p][q].y;
                    f[q*4+2] = rw[p][q].z; f[q*4+3] = rw[p][q].w;
                }
                __nv_bfloat16 h[16], l[16];
                #pragma unroll
                for (int i = 0; i < 16; i++) split1(f[i], h[i], l[i]);
                uint4 uh0 = make_uint4(pk2(h[0],h[1]), pk2(h[2],h[3]), pk2(h[4],h[5]), pk2(h[6],h[7]));
                uint4 uh1 = make_uint4(pk2(h[8],h[9]), pk2(h[10],h[11]), pk2(h[12],h[13]), pk2(h[14],h[15]));
                uint4 ul0 = make_uint4(pk2(l[0],l[1]), pk2(l[2],l[3]), pk2(l[4],l[5]), pk2(l[6],l[7]));
                uint4 ul1 = make_uint4(pk2(l[8],l[9]), pk2(l[10],l[11]), pk2(l[12],l[13]), pk2(l[14],l[15]));
                long o = p * 5120 + lw * 40 + wk;
                *(uint4*)&pWh[o] = uh0; *(uint4*)&pWh[o + 8] = uh1;
                *(uint4*)&pWl[o] = ul0; *(uint4*)&pWl[o + 8] = ul1;
            }
            if (t + p + 2 < tiles) {
                rah[p] = *(const unsigned*)(Agh + (t + p + 2) * 32);
                ral[p] = *(const unsigned*)(Agl + (t + p + 2) * 32);
                #pragma unroll
                for (int q = 0; q < 4; q++)
                    rw[p][q] = *(const float4*)(Wg + (t + p + 2) * 32 + q * 4);
            }
            __syncthreads();
            #pragma unroll
            for (int k16 = 0; k16 < 2; k16++) {
                int kc = k16 * 16 + tc * 2;
                unsigned ah0 = *(const unsigned*)&pAh[p * 640 + gr * 40 + kc];
                unsigned ah1 = *(const unsigned*)&pAh[p * 640 + (gr + 8) * 40 + kc];
                unsigned ah2 = *(const unsigned*)&pAh[p * 640 + gr * 40 + kc + 8];
                unsigned ah3 = *(const unsigned*)&pAh[p * 640 + (gr + 8) * 40 + kc + 8];
                unsigned al0 = *(const unsigned*)&pAl[p * 640 + gr * 40 + kc];
                unsigned al1 = *(const unsigned*)&pAl[p * 640 + (gr + 8) * 40 + kc];
                unsigned al2 = *(const unsigned*)&pAl[p * 640 + gr * 40 + kc + 8];
                unsigned al3 = *(const unsigned*)&pAl[p * 640 + (gr + 8) * 40 + kc + 8];
                #pragma unroll
                for (int j = 0; j < 2; j++) {
                    int n = warp * 16 + j * 8 + gr;
                    unsigned bh0 = *(const unsigned*)&pWh[p * 5120 + n * 40 + kc];
                    unsigned bh1 = *(const unsigned*)&pWh[p * 5120 + n * 40 + kc + 8];
                    unsigned bl0 = *(const unsigned*)&pWl[p * 5120 + n * 40 + kc];
                    unsigned bl1 = *(const unsigned*)&pWl[p * 5120 + n * 40 + kc + 8];
                    mma16816(acc[j][0], acc[j][1], acc[j][2], acc[j][3],
                             ah0, ah1, ah2, ah3, bh0, bh1);
                    mma16816(acc[j][0], acc[j][1], acc[j][2], acc[j][3],
                             ah0, ah1, ah2, ah3, bl0, bl1);
                    mma16816(acc[j][0], acc[j][1], acc[j][2], acc[j][3],
                             al0, al1, al2, al3, bh0, bh1);
                }
            }
            __syncthreads();
        }
    }

    #pragma unroll
    for (int j = 0; j < 2; j++) {
        int col = warp * 16 + j * 8 + tc * 2;
        Csm[gr * 132 + col] = acc[j][0];
        Csm[gr * 132 + col + 1] = acc[j][1];
        Csm[(gr + 8) * 132 + col] = acc[j][2];
        Csm[(gr + 8) * 132 + col + 1] = acc[j][3];
    }
    __syncthreads();

    #pragma unroll
    for (int it = 0; it < 4; it++) {
        int idx = tid + it * 256;
        int m = idx >> 6, n = idx & 63;
        if (m0 + m < cnt) {
            float gg = Csm[m * 132 + n];
            float uu = Csm[m * 132 + 64 + n];
            float a = gg / (1.f + expf(-gg)) * uu;
            __nv_bfloat16 h, l; split1(a, h, l);
            long o = (long)(e * BATCH + m0 + m) * IDIM + ib + n;
            g_acth[o] = h; g_actl[o] = l;
        }
    }
}

// ---------------- MoE w2 (tensor, bf16x3, weighted scatter) ----------------
__global__ __launch_bounds__(128) void moe_w2_tc(const float* __restrict__ w2)
{
    int e = blockIdx.y;
    int cnt = g_cnt[e];
    int m0 = blockIdx.z * 16;
    if (m0 >= cnt) return;
    int hb = blockIdx.x * 64;

    __shared__ __nv_bfloat16 sAh[2][16][40], sAl[2][16][40];
    __shared__ __nv_bfloat16 sWh[2][64][40], sWl[2][64][40];

    int tid = threadIdx.x, lane = tid & 31, warp = tid >> 5;
    int gr = lane >> 2, tc = lane & 3;

    int ar = tid >> 3, akp = (tid & 7) * 4;
    const __nv_bfloat16* Agh = g_acth + (long)(e * BATCH + m0 + ar) * IDIM + akp;
    const __nv_bfloat16* Agl = g_actl + (long)(e * BATCH + m0 + ar) * IDIM + akp;
    int lw = tid >> 1, wk = (tid & 1) * 16;
    const float* Wg = w2 + ((long)e * HDIM + hb + lw) * IDIM + wk;

    const int tiles = IDIM / 32;
    float acc[2][4] = {};

    uint2 rah[2], ral[2];
    float4 rw[2][4];
    #pragma unroll
    for (int s = 0; s < 2; s++) {
        rah[s] = *(const uint2*)(Agh + s * 32);
        ral[s] = *(const uint2*)(Agl + s * 32);
        #pragma unroll
        for (int q = 0; q < 4; q++) rw[s][q] = *(const float4*)(Wg + s * 32 + q * 4);
    }

    for (int t = 0; t < tiles; t += 2) {
        #pragma unroll
        for (int p = 0; p < 2; p++) {
            *(uint2*)&sAh[p][ar][akp] = rah[p];
            *(uint2*)&sAl[p][ar][akp] = ral[p];
            {
                float f[16];
                #pragma unroll
                for (int q = 0; q < 4; q++) {
                    f[q*4+0] = rw[p][q].x; f[q*4+1] = rw[p][q].y;
                    f[q*4+2] = rw[p][q].z; f[q*4+3] = rw[p][q].w;
                }
                __nv_bfloat16 h[16], l[16];
                #pragma unroll
                for (int i = 0; i < 16; i++) split1(f[i], h[i], l[i]);
                uint4 uh0 = make_uint4(pk2(h[0],h[1]), pk2(h[2],h[3]), pk2(h[4],h[5]), pk2(h[6],h[7]));
                uint4 uh1 = make_uint4(pk2(h[8],h[9]), pk2(h[10],h[11]), pk2(h[12],h[13]), pk2(h[14],h[15]));
                uint4 ul0 = make_uint4(pk2(l[0],l[1]), pk2(l[2],l[3]), pk2(l[4],l[5]), pk2(l[6],l[7]));
                uint4 ul1 = make_uint4(pk2(l[8],l[9]), pk2(l[10],l[11]), pk2(l[12],l[13]), pk2(l[14],l[15]));
                *(uint4*)&sWh[p][lw][wk] = uh0; *(uint4*)&sWh[p][lw][wk + 8] = uh1;
                *(uint4*)&sWl[p][lw][wk] = ul0; *(uint4*)&sWl[p][lw][wk + 8] = ul1;
            }
            if (t + p + 2 < tiles) {
                rah[p] = *(const uint2*)(Agh + (t + p + 2) * 32);
                ral[p] = *(const uint2*)(Agl + (t + p + 2) * 32);
                #pragma unroll
                for (int q = 0; q < 4; q++)
                    rw[p][q] = *(const float4*)(Wg + (t + p + 2) * 32 + q * 4);
            }
            __syncthreads();
            #pragma unroll
            for (int k16 = 0; k16 < 2; k16++) {
                int kc = k16 * 16 + tc * 2;
                unsigned ah0 = *(const unsigned*)&sAh[p][gr][kc];
                unsigned ah1 = *(const unsigned*)&sAh[p][gr + 8][kc];
                unsigned ah2 = *(const unsigned*)&sAh[p][gr][kc + 8];
                unsigned ah3 = *(const unsigned*)&sAh[p][gr + 8][kc + 8];
                unsigned al0 = *(const unsigned*)&sAl[p][gr][kc];
                unsigned al1 = *(const unsigned*)&sAl[p][gr + 8][kc];
                unsigned al2 = *(const unsigned*)&sAl[p][gr][kc + 8];
                unsigned al3 = *(const unsigned*)&sAl[p][gr + 8][kc + 8];
                #pragma unroll
                for (int j = 0; j < 2; j++) {
                    int n = warp * 16 + j * 8 + gr;
                    unsigned bh0 = *(const unsigned*)&sWh[p][n][kc];
                    unsigned bh1 = *(const unsigned*)&sWh[p][n][kc + 8];
                    unsigned bl0 = *(const unsigned*)&sWl[p][n][kc];
                    unsigned bl1 = *(const unsigned*)&sWl[p][n][kc + 8];
                    mma16816(acc[j][0], acc[j][1], acc[j][2], acc[j][3],
                             ah0, ah1, ah2, ah3, bh0, bh1);
                    mma16816(acc[j][0], acc[j][1], acc[j][2], acc[j][3],
                             ah0, ah1, ah2, ah3, bl0, bl1);
                    mma16816(acc[j][0], acc[j][1], acc[j][2], acc[j][3],
                             al0, al1, al2, al3, bh0, bh1);
                }
            }
            __syncthreads();
        }
    }

    #pragma unroll
    for (int j = 0; j < 2; j++) {
        int col = hb + warp * 16 + j * 8 + tc * 2;
        int m1 = m0 + gr, m2 = m0 + gr + 8;
        if (m1 < cnt) {
            int tok = g_tok[e * BATCH + m1], sj = g_slot[e * BATCH + m1];
            float w = g_wt[e * BATCH + m1];
            float* yp = &g_ypair[(long)(tok * TOPK + sj) * HDIM + col];
            yp[0] = w * acc[j][0]; yp[1] = w * acc[j][1];
        }
        if (m2 < cnt) {
            int tok = g_tok[e * BATCH + m2], sj = g_slot[e * BATCH + m2];
            float w = g_wt[e * BATCH + m2];
            float* yp = &g_ypair[(long)(tok * TOPK + sj) * HDIM + col];
            yp[0] = w * acc[j][2]; yp[1] = w * acc[j][3];
        }
    }
}

// ---------------- finalize ----------------
__global__ __launch_bounds__(256) void finalize_k(float* __restrict__ out)
{
    int idx = blockIdx.x * 256 + threadIdx.x;
    int tok = idx >> 11, hh = idx & (HDIM - 1);
    float s = g_hs2[idx];
    #pragma unroll
    for (int j = 0; j < TOPK; j++) s += g_ypair[(tok * TOPK + j) * HDIM + hh];
    out[idx] = s;
}

// ---------------- launch ----------------
extern "C" void kernel_launch(void* const* d_in, const int* in_sizes, int n_in,
                              void* d_out, int out_size)
{
    static float *p_hn = 0, *p_qkv = 0, *p_hs2 = 0, *p_h2 = 0, *p_part = 0;
    static __nv_bfloat16 *p_hnh = 0, *p_hnl = 0, *p_ath = 0, *p_atl = 0, *p_h2h = 0, *p_h2l = 0;
    if (!p_hn) {
        cudaGetSymbolAddress((void**)&p_hn,   g_hn);
        cudaGetSymbolAddress((void**)&p_qkv,  g_qkv);
        cudaGetSymbolAddress((void**)&p_hs2,  g_hs2);
        cudaGetSymbolAddress((void**)&p_h2,   g_h2);
        cudaGetSymbolAddress((void**)&p_part, g_part);
        cudaGetSymbolAddress((void**)&p_hnh,  g_hnh);
        cudaGetSymbolAddress((void**)&p_hnl,  g_hnl);
        cudaGetSymbolAddress((void**)&p_ath,  g_ath);
        cudaGetSymbolAddress((void**)&p_atl,  g_atl);
        cudaGetSymbolAddress((void**)&p_h2h,  g_h2h);
        cudaGetSymbolAddress((void**)&p_h2l,  g_h2l);
        cudaFuncSetAttribute(attn_part_tc,
                             cudaFuncAttributeMaxDynamicSharedMemorySize, ASM_TOT);
    }

    const float *hidden = 0, *k_cache = 0, *v_cache = 0, *w_qkv = 0, *b_qkv = 0;
    const float *w_o = 0, *ln1_w = 0, *ln2_w = 0, *gate_w = 0, *w1 = 0, *w2 = 0;
    const int *positions = 0, *seqlens = 0;

    for (int i = 0; i < n_in; i++) {
        long sz = (long)in_sizes[i];
        const void* p = d_in[i];
        if      (sz == (long)BATCH * HDIM)            hidden = (const float*)p;
        else if (sz == (long)BATCH) {
            if (!positions) positions = (const int*)p; else seqlens = (const int*)p;
        }
        else if (sz == (long)BATCH * SEQ * NKV * HD) {
            if (!k_cache) k_cache = (const float*)p; else v_cache = (const float*)p;
        }
        else if (sz == (long)QKV_N * HDIM)            w_qkv  = (const float*)p;
        else if (sz == (long)QKV_N)                   b_qkv  = (const float*)p;
        else if (sz == (long)HDIM * NH * HD)          w_o    = (const float*)p;
        else if (sz == (long)HDIM) {
            if (!ln1_w) ln1_w = (const float*)p; else ln2_w = (const float*)p;
        }
        else if (sz == (long)NEXP * HDIM)             gate_w = (const float*)p;
        else if (sz == (long)NEXP * 2 * IDIM * HDIM)  w1     = (const float*)p;
        else if (sz == (long)NEXP * HDIM * IDIM)      w2     = (const float*)p;
    }
    if (!seqlens && positions) seqlens = positions;
    if (!v_cache) v_cache = k_cache;
    if (!ln2_w)   ln2_w   = ln1_w;

    float* out = (float*)d_out;

    reset_k<<<1, 32>>>();
    rmsnorm_k<<<BATCH, 256>>>(hidden, ln1_w, p_hn, p_hnh, p_hnl);
    gemm_part_tc<<<dim3(QKV_N / 64, 4), 256>>>(p_hnh, p_hnl, w_qkv, p_part, QKV_N, HDIM, 4);
    gemm_reduce_k<<<(64 * QKV_N) / 1024, 256>>>(p_part, b_qkv, nullptr, p_qkv, QKV_N, 4);
    attn_part_tc<<<dim3(NCHUNK, NKV, BATCH), 256, ASM_TOT>>>(k_cache, v_cache, seqlens);
    attn_comb_k<<<BATCH * NKV, 256>>>(seqlens, p_ath, p_atl);
    gemm_part_tc<<<dim3(HDIM / 64, 8), 256>>>(p_ath, p_atl, w_o, p_part, HDIM, NH * HD, 8);
    gemm_reduce_k<<<(64 * HDIM) / 1024, 256>>>(p_part, nullptr, hidden, p_hs2, HDIM, 8);
    rmsnorm_k<<<BATCH, 256>>>(p_hs2, ln2_w, p_h2, p_h2h, p_h2l);
    gate_k<<<BATCH, 256>>>(gate_w);
    moe_w1_tc<<<dim3(IDIM / 64, NEXP, 4), 256>>>(w1);
    moe_w2_tc<<<dim3(HDIM / 64, NEXP, 4), 128>>>(w2);
    finalize_k<<<(BATCH * HDIM) / 256, 256>>>(out);
}

// round 15
// speedup vs baseline: 1.0320x; 1.0320x over previous
#include <cuda_runtime.h>
#include <cuda_bf16.h>
#include <math.h>

// ---------------- problem constants ----------------
#define BATCH 64
#define HDIM  2048
#define SEQ   2048
#define NH    32
#define NKV   4
#define GQA   8
#define HD    128
#define NEXP  32
#define IDIM  768
#define TOPK  4
#define QKV_N 5120
#define EPS   1e-6f
#define SCHUNK 256
#define NCHUNK (SEQ / SCHUNK)
#define PD 4

// ---------------- scratch (device globals) ----------------
// args must come from cudaGetSymbolAddress (ATS host-shadow bug, rounds 1-5).
__device__ float g_hn   [BATCH * HDIM];
__device__ float g_qkv  [BATCH * QKV_N];
__device__ float g_hs2  [BATCH * HDIM];
__device__ float g_h2   [BATCH * HDIM];
__device__ float g_ypair[BATCH * TOPK * HDIM];
__device__ float g_part [4 * BATCH * QKV_N];
__device__ int   g_cnt  [NEXP];
__device__ int   g_tok  [NEXP * BATCH];
__device__ int   g_slot [NEXP * BATCH];
__device__ float g_wt   [NEXP * BATCH];
__device__ float g_pm [BATCH * NKV * NCHUNK * GQA];
__device__ float g_pl [BATCH * NKV * NCHUNK * GQA];
__device__ float g_po [BATCH * NKV * NCHUNK * GQA * HD];
// bf16 split activations
__device__ __nv_bfloat16 g_hnh [BATCH * HDIM];
__device__ __nv_bfloat16 g_hnl [BATCH * HDIM];
__device__ __nv_bfloat16 g_ath [BATCH * NH * HD];
__device__ __nv_bfloat16 g_atl [BATCH * NH * HD];
__device__ __nv_bfloat16 g_h2h [BATCH * HDIM];
__device__ __nv_bfloat16 g_h2l [BATCH * HDIM];
__device__ __nv_bfloat16 g_acth[NEXP * BATCH * IDIM];
__device__ __nv_bfloat16 g_actl[NEXP * BATCH * IDIM];

// ---------------- helpers ----------------
__device__ __forceinline__ void split1(float f, __nv_bfloat16& h, __nv_bfloat16& l) {
    h = __float2bfloat16(f);
    l = __float2bfloat16(f - __bfloat162float(h));
}
__device__ __forceinline__ unsigned pk2(__nv_bfloat16 a, __nv_bfloat16 b) {
    __nv_bfloat162 h; h.x = a; h.y = b;
    return *reinterpret_cast<unsigned*>(&h);
}
__device__ __forceinline__ void mma16816(
    float& c0, float& c1, float& c2, float& c3,
    unsigned a0, unsigned a1, unsigned a2, unsigned a3,
    unsigned b0, unsigned b1)
{
    asm volatile(
        "mma.sync.aligned.m16n8k16.row.col.f32.bf16.bf16.f32 "
        "{%0,%1,%2,%3},{%4,%5,%6,%7},{%8,%9},{%0,%1,%2,%3};"
        : "+f"(c0), "+f"(c1), "+f"(c2), "+f"(c3)
        : "r"(a0), "r"(a1), "r"(a2), "r"(a3), "r"(b0), "r"(b1));
}

// ---------------- reset ----------------
__global__ void reset_k() {
    if (threadIdx.x < NEXP) g_cnt[threadIdx.x] = 0;
}

// ---------------- RMSNorm: fp32 + bf16 split out ----------------
__global__ __launch_bounds__(256) void rmsnorm_k(
    const float* __restrict__ x, const float* __restrict__ w,
    float* __restrict__ y, __nv_bfloat16* __restrict__ yh, __nv_bfloat16* __restrict__ yl)
{
    int b = blockIdx.x, tid = threadIdx.x;
    const float* xb = x + b * HDIM;
    float s = 0.f;
    for (int i = tid; i < HDIM; i += 256) { float v = xb[i]; s += v * v; }
    for (int o = 16; o; o >>= 1) s += __shfl_xor_sync(0xffffffffu, s, o);
    __shared__ float red[8];
    __shared__ float inv;
    if ((tid & 31) == 0) red[tid >> 5] = s;
    __syncthreads();
    if (tid == 0) {
        float t = 0.f;
        #pragma unroll
        for (int i = 0; i < 8; i++) t += red[i];
        inv = rsqrtf(t * (1.f / HDIM) + EPS);
    }
    __syncthreads();
    float iv = inv;
    for (int i = tid; i < HDIM; i += 256) {
        float v = xb[i] * iv * w[i];
        y[b * HDIM + i] = v;
        __nv_bfloat16 h, l; split1(v, h, l);
        yh[b * HDIM + i] = h; yl[b * HDIM + i] = l;
    }
}

// ---------------- tensor GEMM partial (bf16x3), PD=4 dynamic smem -------------
// 81920 B dynamic: sAh[4][2560], sAl, sWh, sWl (2560 = 64*40 elems/stage)
__global__ __launch_bounds__(256) void gemm_part_tc(
    const __nv_bfloat16* __restrict__ Ah, const __nv_bfloat16* __restrict__ Al,
    const float* __restrict__ W, float* __restrict__ part, int N, int K, int ksplit)
{
    extern __shared__ char dsm[];
    __nv_bfloat16* sAh = (__nv_bfloat16*)dsm;
    __nv_bfloat16* sAl = sAh + PD * 2560;
    __nv_bfloat16* sWh = sAl + PD * 2560;
    __nv_bfloat16* sWl = sWh + PD * 2560;

    int nb = blockIdx.x * 64;
    int ks = blockIdx.y;
    int klen = K / ksplit, kbeg = ks * klen, tiles = klen / 32;
    int tid = threadIdx.x, lane = tid & 31, warp = tid >> 5;
    int mw = warp & 3, nw = warp >> 2;
    int gr = lane >> 2, tc = lane & 3;

    int lm = tid >> 2, lk8 = (tid & 3) * 8;
    const __nv_bfloat16* Agh = Ah + (long)lm * K + kbeg + lk8;
    const __nv_bfloat16* Agl = Al + (long)lm * K + kbeg + lk8;
    const float* Wg = W + (long)(nb + lm) * K + kbeg + lk8;

    float acc[4][4] = {};
    uint4 rah[PD], ral[PD];
    float4 rw[PD][2];
    #pragma unroll
    for (int s = 0; s < PD; s++) {
        rah[s] = *(const uint4*)(Agh + s * 32);
        ral[s] = *(const uint4*)(Agl + s * 32);
        rw[s][0] = *(const float4*)(Wg + s * 32);
        rw[s][1] = *(const float4*)(Wg + s * 32 + 4);
    }

    for (int t = 0; t < tiles; t += PD) {
        #pragma unroll
        for (int p = 0; p < PD; p++) {
            *(uint4*)&sAh[p * 2560 + lm * 40 + lk8] = rah[p];
            *(uint4*)&sAl[p * 2560 + lm * 40 + lk8] = ral[p];
            {
                float f[8] = {rw[p][0].x, rw[p][0].y, rw[p][0].z, rw[p][0].w,
                              rw[p][1].x, rw[p][1].y, rw[p][1].z, rw[p][1].w};
                __nv_bfloat16 h[8], l[8];
                #pragma unroll
                for (int i = 0; i < 8; i++) split1(f[i], h[i], l[i]);
                uint4 uh = make_uint4(pk2(h[0],h[1]), pk2(h[2],h[3]), pk2(h[4],h[5]), pk2(h[6],h[7]));
                uint4 ul = make_uint4(pk2(l[0],l[1]), pk2(l[2],l[3]), pk2(l[4],l[5]), pk2(l[6],l[7]));
                *(uint4*)&sWh[p * 2560 + lm * 40 + lk8] = uh;
                *(uint4*)&sWl[p * 2560 + lm * 40 + lk8] = ul;
            }
            if (t + p + PD < tiles) {
                rah[p] = *(const uint4*)(Agh + (t + p + PD) * 32);
                ral[p] = *(const uint4*)(Agl + (t + p + PD) * 32);
                rw[p][0] = *(const float4*)(Wg + (t + p + PD) * 32);
                rw[p][1] = *(const float4*)(Wg + (t + p + PD) * 32 + 4);
            }
            __syncthreads();
            #pragma unroll
            for (int k16 = 0; k16 < 2; k16++) {
                int kc = k16 * 16 + tc * 2;
                int ra = mw * 16 + gr;
                unsigned ah0 = *(const unsigned*)&sAh[p * 2560 + ra * 40 + kc];
                unsigned ah1 = *(const unsigned*)&sAh[p * 2560 + (ra + 8) * 40 + kc];
                unsigned ah2 = *(const unsigned*)&sAh[p * 2560 + ra * 40 + kc + 8];
                unsigned ah3 = *(const unsigned*)&sAh[p * 2560 + (ra + 8) * 40 + kc + 8];
                unsigned al0 = *(const unsigned*)&sAl[p * 2560 + ra * 40 + kc];
                unsigned al1 = *(const unsigned*)&sAl[p * 2560 + (ra + 8) * 40 + kc];
                unsigned al2 = *(const unsigned*)&sAl[p * 2560 + ra * 40 + kc + 8];
                unsigned al3 = *(const unsigned*)&sAl[p * 2560 + (ra + 8) * 40 + kc + 8];
                #pragma unroll
                for (int j = 0; j < 4; j++) {
                    int n = nw * 32 + j * 8 + gr;
                    unsigned bh0 = *(const unsigned*)&sWh[p * 2560 + n * 40 + kc];
                    unsigned bh1 = *(const unsigned*)&sWh[p * 2560 + n * 40 + kc + 8];
                    unsigned bl0 = *(const unsigned*)&sWl[p * 2560 + n * 40 + kc];
                    unsigned bl1 = *(const unsigned*)&sWl[p * 2560 + n * 40 + kc + 8];
                    mma16816(acc[j][0], acc[j][1], acc[j][2], acc[j][3],
                             ah0, ah1, ah2, ah3, bh0, bh1);
                    mma16816(acc[j][0], acc[j][1], acc[j][2], acc[j][3],
                             ah0, ah1, ah2, ah3, bl0, bl1);
                    mma16816(acc[j][0], acc[j][1], acc[j][2], acc[j][3],
                             al0, al1, al2, al3, bh0, bh1);
                }
            }
            __syncthreads();
        }
    }

    #pragma unroll
    for (int j = 0; j < 4; j++) {
        int col = nb + nw * 32 + j * 8 + tc * 2;
        long r0 = (long)(ks * 64 + mw * 16 + gr) * N + col;
        *(float2*)&part[r0] = make_float2(acc[j][0], acc[j][1]);
        *(float2*)&part[r0 + 8L * N] = make_float2(acc[j][2], acc[j][3]);
    }
}

// ---------------- GEMM reduce ----------------
__global__ __launch_bounds__(256) void gemm_reduce_k(
    const float* __restrict__ part, const float* __restrict__ bias,
    const float* __restrict__ res, float* __restrict__ C, int N, int ksplit)
{
    int idx = (blockIdx.x * 256 + threadIdx.x) * 4;
    int m = idx / N, n = idx % N;
    float4 s = bias ? *(const float4*)&bias[n] : make_float4(0.f, 0.f, 0.f, 0.f);
    for (int ks = 0; ks < ksplit; ks++) {
        float4 p = *(const float4*)&part[((long)(ks * 64 + m)) * N + n];
        s.x += p.x; s.y += p.y; s.z += p.z; s.w += p.w;
    }
    if (res) {
        float4 r = *(const float4*)&res[idx];
        s.x += r.x; s.y += r.y; s.z += r.z; s.w += r.w;
    }
    *(float4*)&C[idx] = s;
}

// ---------------- split-S GQA flash-decode (scalar, r13-proven) ----------------
__global__ __launch_bounds__(256) void attn_part_k(
    const float* __restrict__ kc, const float* __restrict__ vc,
    const int* __restrict__ seq_lens)
{
    int c  = blockIdx.x;
    int kv = blockIdx.y;
    int b  = blockIdx.z;
    int tid = threadIdx.x, warp = tid >> 5, lane = tid & 31;
    int sl = seq_lens[b];
    if (sl < 0) sl = 0;
    if (sl > SEQ - 1) sl = SEQ - 1;
    int L  = sl + 1;
    int s0 = c * SCHUNK;
    if (s0 >= L) return;
    int s1 = s0 + SCHUNK; if (s1 > L) s1 = L;
    const float scale = 0.08838834764831845f;

    const float* qbase = g_qkv + b * QKV_N + kv * GQA * HD;
    const float* knew  = g_qkv + b * QKV_N + NH * HD + kv * HD;
    const float* vnew  = g_qkv + b * QKV_N + (NH + NKV) * HD + kv * HD;

    float4 q[GQA];
    #pragma unroll
    for (int h = 0; h < GQA; h++) q[h] = *(const float4*)(qbase + h * HD + lane * 4);

    float m[GQA], l[GQA];
    float4 o[GQA];
    #pragma unroll
    for (int h = 0; h < GQA; h++) {
        m[h] = -INFINITY; l[h] = 0.f; o[h] = make_float4(0.f, 0.f, 0.f, 0.f);
    }

    int s = s0 + warp;
    if (s < s1) {
        const float* kp = (s == sl) ? knew : (kc + ((size_t)(b * SEQ + s) * NKV + kv) * HD);
        const float* vp = (s == sl) ? vnew : (vc + ((size_t)(b * SEQ + s) * NKV + kv) * HD);
        float4 kk = *(const float4*)(kp + lane * 4);
        float4 vv = *(const float4*)(vp + lane * 4);
        for (;;) {
            int sn = s + 8;
            float4 knx, vnx;
            if (sn < s1) {
                const float* kp2 = (sn == sl) ? knew : (kc + ((size_t)(b * SEQ + sn) * NKV + kv) * HD);
                const float* vp2 = (sn == sl) ? vnew : (vc + ((size_t)(b * SEQ + sn) * NKV + kv) * HD);
                knx = *(const float4*)(kp2 + lane * 4);
                vnx = *(const float4*)(vp2 + lane * 4);
            }
            #pragma unroll
            for (int h = 0; h < GQA; h++) {
                float d = q[h].x * kk.x + q[h].y * kk.y + q[h].z * kk.z + q[h].w * kk.w;
                d += __shfl_xor_sync(0xffffffffu, d, 16);
                d += __shfl_xor_sync(0xffffffffu, d, 8);
                d += __shfl_xor_sync(0xffffffffu, d, 4);
                d += __shfl_xor_sync(0xffffffffu, d, 2);
                d += __shfl_xor_sync(0xffffffffu, d, 1);
                float sc = d * scale;
                float nm = fmaxf(m[h], sc);
                float corr = __expf(m[h] - nm);
                float p = __expf(sc - nm);
                l[h] = l[h] * corr + p;
                o[h].x = o[h].x * corr + p * vv.x;
                o[h].y = o[h].y * corr + p * vv.y;
                o[h].z = o[h].z * corr + p * vv.z;
                o[h].w = o[h].w * corr + p * vv.w;
                m[h] = nm;
            }
            if (sn >= s1) break;
            s = sn; kk = knx; vv = vnx;
        }
    }

    __shared__ float sm[8][GQA], sll[8][GQA];
    __shared__ float so[8][GQA][HD];
    #pragma unroll
    for (int h = 0; h < GQA; h++) {
        if (lane == 0) { sm[warp][h] = m[h]; sll[warp][h] = l[h]; }
        *(float4*)&so[warp][h][lane * 4] = o[h];
    }
    __syncthreads();

    int pbase = ((b * NKV + kv) * NCHUNK + c) * GQA;
    for (int idx = tid; idx < GQA * HD; idx += 256) {
        int h = idx >> 7, d = idx & (HD - 1);
        float M = -INFINITY;
        #pragma unroll
        for (int w = 0; w < 8; w++) M = fmaxf(M, sm[w][h]);
        float acc = 0.f, Ls = 0.f;
        #pragma unroll
        for (int w = 0; w < 8; w++) {
            float cw = __expf(sm[w][h] - M);
            acc += cw * so[w][h][d];
            Ls  += cw * sll[w][h];
        }
        g_po[(pbase + h) * HD + d] = acc;
        if (d == 0) { g_pm[pbase + h] = M; g_pl[pbase + h] = Ls; }
    }
}

// ---------------- combine split-S partials -> bf16 split ----------------
__global__ __launch_bounds__(256) void attn_comb_k(
    const int* __restrict__ seq_lens,
    __nv_bfloat16* __restrict__ outh, __nv_bfloat16* __restrict__ outl)
{
    int b  = blockIdx.x >> 2;
    int kv = blockIdx.x & 3;
    int tid = threadIdx.x;
    int sl = seq_lens[b];
    if (sl < 0) sl = 0;
    if (sl > SEQ - 1) sl = SEQ - 1;
    int nch = sl / SCHUNK + 1;
    int base = (b * NKV + kv) * NCHUNK;

    for (int idx = tid; idx < GQA * HD; idx += 256) {
        int h = idx >> 7, d = idx & (HD - 1);
        float M = -INFINITY;
        for (int c = 0; c < nch; c++) M = fmaxf(M, g_pm[(base + c) * GQA + h]);
        float acc = 0.f, Ls = 0.f;
        for (int c = 0; c < nch; c++) {
            float w = __expf(g_pm[(base + c) * GQA + h] - M);
            acc += w * g_po[((base + c) * GQA + h) * HD + d];
            Ls  += w * g_pl[(base + c) * GQA + h];
        }
        float v = acc / Ls;
        __nv_bfloat16 hh, ll; split1(v, hh, ll);
        long o = (long)b * NH * HD + (kv * GQA + h) * HD + d;
        outh[o] = hh; outl[o] = ll;
    }
}

// ---------------- gate ----------------
__global__ __launch_bounds__(256) void gate_k(const float* __restrict__ gw)
{
    int b = blockIdx.x, tid = threadIdx.x, warp = tid >> 5, lane = tid & 31;
    __shared__ float lg[NEXP];
    const float* h = g_h2 + b * HDIM;
    for (int e = warp; e < NEXP; e += 8) {
        const float* g = gw + e * HDIM;
        float s = 0.f;
        for (int i = lane; i < HDIM; i += 32) s += h[i] * g[i];
        for (int o = 16; o; o >>= 1) s += __shfl_xor_sync(0xffffffffu, s, o);
        if (lane == 0) lg[e] = s;
    }
    __syncthreads();
    if (tid == 0) {
        float val[TOPK]; int idx[TOPK];
        unsigned used = 0;
        for (int j = 0; j < TOPK; j++) {
            float best = -1e30f; int bi = 0;
            for (int e = 0; e < NEXP; e++)
                if (!((used >> e) & 1u) && lg[e] > best) { best = lg[e]; bi = e; }
            used |= 1u << bi; val[j] = best; idx[j] = bi;
        }
        float s = 0.f, wj[TOPK];
        for (int j = 0; j < TOPK; j++) { wj[j] = expf(val[j] - val[0]); s += wj[j]; }
        float is = 1.f / s;
        for (int j = 0; j < TOPK; j++) {
            int e = idx[j];
            int pos = atomicAdd(&g_cnt[e], 1);
            g_tok [e * BATCH + pos] = b;
            g_slot[e * BATCH + pos] = j;
            g_wt  [e * BATCH + pos] = wj[j] * is;
        }
    }
}

// ---------------- MoE w1 (tensor, bf16x3, fused SwiGLU), PD=4 dyn smem ---------
// dyn smem 92160 B: pAh[4][640], pAl[4][640], pWh[4][5120], pWl[4][5120]
__global__ __launch_bounds__(256) void moe_w1_tc(const float* __restrict__ w1)
{
    int e = blockIdx.y;
    int cnt = g_cnt[e];
    int m0 = blockIdx.z * 16;
    if (m0 >= cnt) return;
    int ib = blockIdx.x * 64;

    extern __shared__ char dsm[];
    __nv_bfloat16* pAh = (__nv_bfloat16*)dsm;
    __nv_bfloat16* pAl = pAh + PD * 640;
    __nv_bfloat16* pWh = pAl + PD * 640;
    __nv_bfloat16* pWl = pWh + PD * 5120;
    float* Csm = (float*)dsm;                 // [16][132] overlay after mainloop
    __shared__ int toks[16];

    int tid = threadIdx.x, lane = tid & 31, warp = tid >> 5;
    int gr = lane >> 2, tc = lane & 3;
    if (tid < 16) toks[tid] = (m0 + tid < cnt) ? g_tok[e * BATCH + m0 + tid]
                                               : g_tok[e * BATCH];
    __syncthreads();

    int ar = tid >> 4, akp = (tid & 15) * 2;
    const __nv_bfloat16* Agh = g_h2h + (long)toks[ar] * HDIM + akp;
    const __nv_bfloat16* Agl = g_h2l + (long)toks[ar] * HDIM + akp;
    int lw = tid >> 1, wk = (tid & 1) * 16;
    long wrow = (long)e * 2 * IDIM + ((lw < 64) ? (ib + lw) : (IDIM + ib + lw - 64));
    const float* Wg = w1 + wrow * HDIM + wk;

    const int tiles = HDIM / 32;   // 64 (mult of PD)
    float acc[2][4] = {};

    unsigned rah[PD], ral[PD];
    float4 rw[PD][4];
    #pragma unroll
    for (int s = 0; s < PD; s++) {
        rah[s] = *(const unsigned*)(Agh + s * 32);
        ral[s] = *(const unsigned*)(Agl + s * 32);
        #pragma unroll
        for (int q = 0; q < 4; q++) rw[s][q] = *(const float4*)(Wg + s * 32 + q * 4);
    }

    for (int t = 0; t < tiles; t += PD) {
        #pragma unroll
        for (int p = 0; p < PD; p++) {
            *(unsigned*)&pAh[p * 640 + ar * 40 + akp] = rah[p];
            *(unsigned*)&pAl[p * 640 + ar * 40 + akp] = ral[p];
            {
                float f[16];
                #pragma unroll
                for (int q = 0; q < 4; q++) {
                    f[q*4+0] = rw[p][q].x; f[q*4+1] = rw[p][q].y;
                    f[q*4+2] = rw[p][q].z; f[q*4+3] = rw[p][q].w;
                }
                __nv_bfloat16 h[16], l[16];
                #pragma unroll
                for (int i = 0; i < 16; i++) split1(f[i], h[i], l[i]);
                uint4 uh0 = make_uint4(pk2(h[0],h[1]), pk2(h[2],h[3]), pk2(h[4],h[5]), pk2(h[6],h[7]));
                uint4 uh1 = make_uint4(pk2(h[8],h[9]), pk2(h[10],h[11]), pk2(h[12],h[13]), pk2(h[14],h[15]));
                uint4 ul0 = make_uint4(pk2(l[0],l[1]), pk2(l[2],l[3]), pk2(l[4],l[5]), pk2(l[6],l[7]));
                uint4 ul1 = make_uint4(pk2(l[8],l[9]), pk2(l[10],l[11]), pk2(l[12],l[13]), pk2(l[14],l[15]));
                long o = p * 5120 + lw * 40 + wk;
                *(uint4*)&pWh[o] = uh0; *(uint4*)&pWh[o + 8] = uh1;
                *(uint4*)&pWl[o] = ul0; *(uint4*)&pWl[o + 8] = ul1;
            }
            if (t + p + PD < tiles) {
                rah[p] = *(const unsigned*)(Agh + (t + p + PD) * 32);
                ral[p] = *(const unsigned*)(Agl + (t + p + PD) * 32);
                #pragma unroll
                for (int q = 0; q < 4; q++)
                    rw[p][q] = *(const float4*)(Wg + (t + p + PD) * 32 + q * 4);
            }
            __syncthreads();
            #pragma unroll
            for (int k16 = 0; k16 < 2; k16++) {
                int kc = k16 * 16 + tc * 2;
                unsigned ah0 = *(const unsigned*)&pAh[p * 640 + gr * 40 + kc];
                unsigned ah1 = *(const unsigned*)&pAh[p * 640 + (gr + 8) * 40 + kc];
                unsigned ah2 = *(const unsigned*)&pAh[p * 640 + gr * 40 + kc + 8];
                unsigned ah3 = *(const unsigned*)&pAh[p * 640 + (gr + 8) * 40 + kc + 8];
                unsigned al0 = *(const unsigned*)&pAl[p * 640 + gr * 40 + kc];
                unsigned al1 = *(const unsigned*)&pAl[p * 640 + (gr + 8) * 40 + kc];
                unsigned al2 = *(const unsigned*)&pAl[p * 640 + gr * 40 + kc + 8];
                unsigned al3 = *(const unsigned*)&pAl[p * 640 + (gr + 8) * 40 + kc + 8];
                #pragma unroll
                for (int j = 0; j < 2; j++) {
                    int n = warp * 16 + j * 8 + gr;
                    unsigned bh0 = *(const unsigned*)&pWh[p * 5120 + n * 40 + kc];
                    unsigned bh1 = *(const unsigned*)&pWh[p * 5120 + n * 40 + kc + 8];
                    unsigned bl0 = *(const unsigned*)&pWl[p * 5120 + n * 40 + kc];
                    unsigned bl1 = *(const unsigned*)&pWl[p * 5120 + n * 40 + kc + 8];
                    mma16816(acc[j][0], acc[j][1], acc[j][2], acc[j][3],
                             ah0, ah1, ah2, ah3, bh0, bh1);
                    mma16816(acc[j][0], acc[j][1], acc[j][2], acc[j][3],
                             ah0, ah1, ah2, ah3, bl0, bl1);
                    mma16816(acc[j][0], acc[j][1], acc[j][2], acc[j][3],
                             al0, al1, al2, al3, bh0, bh1);
                }
            }
            __syncthreads();
        }
    }

    #pragma unroll
    for (int j = 0; j < 2; j++) {
        int col = warp * 16 + j * 8 + tc * 2;
        Csm[gr * 132 + col] = acc[j][0];
        Csm[gr * 132 + col + 1] = acc[j][1];
        Csm[(gr + 8) * 132 + col] = acc[j][2];
        Csm[(gr + 8) * 132 + col + 1] = acc[j][3];
    }
    __syncthreads();

    #pragma unroll
    for (int it = 0; it < 4; it++) {
        int idx = tid + it * 256;
        int m = idx >> 6, n = idx & 63;
        if (m0 + m < cnt) {
            float gg = Csm[m * 132 + n];
            float uu = Csm[m * 132 + 64 + n];
            float a = gg / (1.f + expf(-gg)) * uu;
            __nv_bfloat16 h, l; split1(a, h, l);
            long o = (long)(e * BATCH + m0 + m) * IDIM + ib + n;
            g_acth[o] = h; g_actl[o] = l;
        }
    }
}

// ---------------- MoE w2 (tensor, bf16x3, weighted scatter), PD=4 dyn smem -----
// dyn smem 51200 B: sAh[4][640], sAl[4][640], sWh[4][2560], sWl[4][2560]
__global__ __launch_bounds__(128) void moe_w2_tc(const float* __restrict__ w2)
{
    int e = blockIdx.y;
    int cnt = g_cnt[e];
    int m0 = blockIdx.z * 16;
    if (m0 >= cnt) return;
    int hb = blockIdx.x * 64;

    extern __shared__ char dsm[];
    __nv_bfloat16* sAh = (__nv_bfloat16*)dsm;
    __nv_bfloat16* sAl = sAh + PD * 640;
    __nv_bfloat16* sWh = sAl + PD * 640;
    __nv_bfloat16* sWl = sWh + PD * 2560;

    int tid = threadIdx.x, lane = tid & 31, warp = tid >> 5;
    int gr = lane >> 2, tc = lane & 3;

    int ar = tid >> 3, akp = (tid & 7) * 4;
    const __nv_bfloat16* Agh = g_acth + (long)(e * BATCH + m0 + ar) * IDIM + akp;
    const __nv_bfloat16* Agl = g_actl + (long)(e * BATCH + m0 + ar) * IDIM + akp;
    int lw = tid >> 1, wk = (tid & 1) * 16;
    const float* Wg = w2 + ((long)e * HDIM + hb + lw) * IDIM + wk;

    const int tiles = IDIM / 32;   // 24 (mult of PD)
    float acc[2][4] = {};

    uint2 rah[PD], ral[PD];
    float4 rw[PD][4];
    #pragma unroll
    for (int s = 0; s < PD; s++) {
        rah[s] = *(const uint2*)(Agh + s * 32);
        ral[s] = *(const uint2*)(Agl + s * 32);
        #pragma unroll
        for (int q = 0; q < 4; q++) rw[s][q] = *(const float4*)(Wg + s * 32 + q * 4);
    }

    for (int t = 0; t < tiles; t += PD) {
        #pragma unroll
        for (int p = 0; p < PD; p++) {
            *(uint2*)&sAh[p * 640 + ar * 40 + akp] = rah[p];
            *(uint2*)&sAl[p * 640 + ar * 40 + akp] = ral[p];
            {
                float f[16];
                #pragma unroll
                for (int q = 0; q < 4; q++) {
                    f[q*4+0] = rw[p][q].x; f[q*4+1] = rw[p][q].y;
                    f[q*4+2] = rw[p][q].z; f[q*4+3] = rw[p][q].w;
                }
                __nv_bfloat16 h[16], l[16];
                #pragma unroll
                for (int i = 0; i < 16; i++) split1(f[i], h[i], l[i]);
                uint4 uh0 = make_uint4(pk2(h[0],h[1]), pk2(h[2],h[3]), pk2(h[4],h[5]), pk2(h[6],h[7]));
                uint4 uh1 = make_uint4(pk2(h[8],h[9]), pk2(h[10],h[11]), pk2(h[12],h[13]), pk2(h[14],h[15]));
                uint4 ul0 = make_uint4(pk2(l[0],l[1]), pk2(l[2],l[3]), pk2(l[4],l[5]), pk2(l[6],l[7]));
                uint4 ul1 = make_uint4(pk2(l[8],l[9]), pk2(l[10],l[11]), pk2(l[12],l[13]), pk2(l[14],l[15]));
                long o = p * 2560 + lw * 40 + wk;
                *(uint4*)&sWh[o] = uh0; *(uint4*)&sWh[o + 8] = uh1;
                *(uint4*)&sWl[o] = ul0; *(uint4*)&sWl[o + 8] = ul1;
            }
            if (t + p + PD < tiles) {
                rah[p] = *(const uint2*)(Agh + (t + p + PD) * 32);
                ral[p] = *(const uint2*)(Agl + (t + p + PD) * 32);
                #pragma unroll
                for (int q = 0; q < 4; q++)
                    rw[p][q] = *(const float4*)(Wg + (t + p + PD) * 32 + q * 4);
            }
            __syncthreads();
            #pragma unroll
            for (int k16 = 0; k16 < 2; k16++) {
                int kc = k16 * 16 + tc * 2;
                unsigned ah0 = *(const unsigned*)&sAh[p * 640 + gr * 40 + kc];
                unsigned ah1 = *(const unsigned*)&sAh[p * 640 + (gr + 8) * 40 + kc];
                unsigned ah2 = *(const unsigned*)&sAh[p * 640 + gr * 40 + kc + 8];
                unsigned ah3 = *(const unsigned*)&sAh[p * 640 + (gr + 8) * 40 + kc + 8];
                unsigned al0 = *(const unsigned*)&sAl[p * 640 + gr * 40 + kc];
                unsigned al1 = *(const unsigned*)&sAl[p * 640 + (gr + 8) * 40 + kc];
                unsigned al2 = *(const unsigned*)&sAl[p * 640 + gr * 40 + kc + 8];
                unsigned al3 = *(const unsigned*)&sAl[p * 640 + (gr + 8) * 40 + kc + 8];
                #pragma unroll
                for (int j = 0; j < 2; j++) {
                    int n = warp * 16 + j * 8 + gr;
                    unsigned bh0 = *(const unsigned*)&sWh[p * 2560 + n * 40 + kc];
                    unsigned bh1 = *(const unsigned*)&sWh[p * 2560 + n * 40 + kc + 8];
                    unsigned bl0 = *(const unsigned*)&sWl[p * 2560 + n * 40 + kc];
                    unsigned bl1 = *(const unsigned*)&sWl[p * 2560 + n * 40 + kc + 8];
                    mma16816(acc[j][0], acc[j][1], acc[j][2], acc[j][3],
                             ah0, ah1, ah2, ah3, bh0, bh1);
                    mma16816(acc[j][0], acc[j][1], acc[j][2], acc[j][3],
                             ah0, ah1, ah2, ah3, bl0, bl1);
                    mma16816(acc[j][0], acc[j][1], acc[j][2], acc[j][3],
                             al0, al1, al2, al3, bh0, bh1);
                }
            }
            __syncthreads();
        }
    }

    #pragma unroll
    for (int j = 0; j < 2; j++) {
        int col = hb + warp * 16 + j * 8 + tc * 2;
        int m1 = m0 + gr, m2 = m0 + gr + 8;
        if (m1 < cnt) {
            int tok = g_tok[e * BATCH + m1], sj = g_slot[e * BATCH + m1];
            float w = g_wt[e * BATCH + m1];
            float* yp = &g_ypair[(long)(tok * TOPK + sj) * HDIM + col];
            yp[0] = w * acc[j][0]; yp[1] = w * acc[j][1];
        }
        if (m2 < cnt) {
            int tok = g_tok[e * BATCH + m2], sj = g_slot[e * BATCH + m2];
            float w = g_wt[e * BATCH + m2];
            float* yp = &g_ypair[(long)(tok * TOPK + sj) * HDIM + col];
            yp[0] = w * acc[j][2]; yp[1] = w * acc[j][3];
        }
    }
}

// ---------------- finalize ----------------
__global__ __launch_bounds__(256) void finalize_k(float* __restrict__ out)
{
    int idx = blockIdx.x * 256 + threadIdx.x;
    int tok = idx >> 11, hh = idx & (HDIM - 1);
    float s = g_hs2[idx];
    #pragma unroll
    for (int j = 0; j < TOPK; j++) s += g_ypair[(tok * TOPK + j) * HDIM + hh];
    out[idx] = s;
}

// ---------------- launch ----------------
extern "C" void kernel_launch(void* const* d_in, const int* in_sizes, int n_in,
                              void* d_out, int out_size)
{
    static float *p_hn = 0, *p_qkv = 0, *p_hs2 = 0, *p_h2 = 0, *p_part = 0;
    static __nv_bfloat16 *p_hnh = 0, *p_hnl = 0, *p_ath = 0, *p_atl = 0, *p_h2h = 0, *p_h2l = 0;
    if (!p_hn) {
        cudaGetSymbolAddress((void**)&p_hn,   g_hn);
        cudaGetSymbolAddress((void**)&p_qkv,  g_qkv);
        cudaGetSymbolAddress((void**)&p_hs2,  g_hs2);
        cudaGetSymbolAddress((void**)&p_h2,   g_h2);
        cudaGetSymbolAddress((void**)&p_part, g_part);
        cudaGetSymbolAddress((void**)&p_hnh,  g_hnh);
        cudaGetSymbolAddress((void**)&p_hnl,  g_hnl);
        cudaGetSymbolAddress((void**)&p_ath,  g_ath);
        cudaGetSymbolAddress((void**)&p_atl,  g_atl);
        cudaGetSymbolAddress((void**)&p_h2h,  g_h2h);
        cudaGetSymbolAddress((void**)&p_h2l,  g_h2l);
        cudaFuncSetAttribute(gemm_part_tc,
                             cudaFuncAttributeMaxDynamicSharedMemorySize, 81920);
        cudaFuncSetAttribute(moe_w1_tc,
                             cudaFuncAttributeMaxDynamicSharedMemorySize, 92160);
        cudaFuncSetAttribute(moe_w2_tc,
                             cudaFuncAttributeMaxDynamicSharedMemorySize, 51200);
    }

    const float *hidden = 0, *k_cache = 0, *v_cache = 0, *w_qkv = 0, *b_qkv = 0;
    const float *w_o = 0, *ln1_w = 0, *ln2_w = 0, *gate_w = 0, *w1 = 0, *w2 = 0;
    const int *positions = 0, *seqlens = 0;

    for (int i = 0; i < n_in; i++) {
        long sz = (long)in_sizes[i];
        const void* p = d_in[i];
        if      (sz == (long)BATCH * HDIM)            hidden = (const float*)p;
        else if (sz == (long)BATCH) {
            if (!positions) positions = (const int*)p; else seqlens = (const int*)p;
        }
        else if (sz == (long)BATCH * SEQ * NKV * HD) {
            if (!k_cache) k_cache = (const float*)p; else v_cache = (const float*)p;
        }
        else if (sz == (long)QKV_N * HDIM)            w_qkv  = (const float*)p;
        else if (sz == (long)QKV_N)                   b_qkv  = (const float*)p;
        else if (sz == (long)HDIM * NH * HD)          w_o    = (const float*)p;
        else if (sz == (long)HDIM) {
            if (!ln1_w) ln1_w = (const float*)p; else ln2_w = (const float*)p;
        }
        else if (sz == (long)NEXP * HDIM)             gate_w = (const float*)p;
        else if (sz == (long)NEXP * 2 * IDIM * HDIM)  w1     = (const float*)p;
        else if (sz == (long)NEXP * HDIM * IDIM)      w2     = (const float*)p;
    }
    if (!seqlens && positions) seqlens = positions;
    if (!v_cache) v_cache = k_cache;
    if (!ln2_w)   ln2_w   = ln1_w;

    float* out = (float*)d_out;

    reset_k<<<1, 32>>>();
    rmsnorm_k<<<BATCH, 256>>>(hidden, ln1_w, p_hn, p_hnh, p_hnl);
    gemm_part_tc<<<dim3(QKV_N / 64, 4), 256, 81920>>>(p_hnh, p_hnl, w_qkv, p_part, QKV_N, HDIM, 4);
    gemm_reduce_k<<<(64 * QKV_N) / 1024, 256>>>(p_part, b_qkv, nullptr, p_qkv, QKV_N, 4);
    attn_part_k<<<dim3(NCHUNK, NKV, BATCH), 256>>>(k_cache, v_cache, seqlens);
    attn_comb_k<<<BATCH * NKV, 256>>>(seqlens, p_ath, p_atl);
    gemm_part_tc<<<dim3(HDIM / 64, 8), 256, 81920>>>(p_ath, p_atl, w_o, p_part, HDIM, NH * HD, 8);
    gemm_reduce_k<<<(64 * HDIM) / 1024, 256>>>(p_part, nullptr, hidden, p_hs2, HDIM, 8);
    rmsnorm_k<<<BATCH, 256>>>(p_hs2, ln2_w, p_h2, p_h2h, p_h2l);
    gate_k<<<BATCH, 256>>>(gate_w);
    moe_w1_tc<<<dim3(IDIM / 64, NEXP, 4), 256, 92160>>>(w1);
    moe_w2_tc<<<dim3(HDIM / 64, NEXP, 4), 128, 51200>>>(w2);
    finalize_k<<<(BATCH * HDIM) / 256, 256>>>(out);
}

// round 16
// speedup vs baseline: 1.1078x; 1.0735x over previous
#include <cuda_runtime.h>
#include <cuda_bf16.h>
#include <math.h>

// ---------------- problem constants ----------------
#define BATCH 64
#define HDIM  2048
#define SEQ   2048
#define NH    32
#define NKV   4
#define GQA   8
#define HD    128
#define NEXP  32
#define IDIM  768
#define TOPK  4
#define QKV_N 5120
#define EPS   1e-6f
#define SCHUNK 256
#define NCHUNK (SEQ / SCHUNK)

// ---------------- scratch (device globals) ----------------
// args must come from cudaGetSymbolAddress (ATS host-shadow bug, rounds 1-5).
__device__ float g_hn   [BATCH * HDIM];
__device__ float g_qkv  [BATCH * QKV_N];
__device__ float g_hs2  [BATCH * HDIM];
__device__ float g_h2   [BATCH * HDIM];
__device__ float g_ypair[BATCH * TOPK * HDIM];
__device__ float g_part [4 * BATCH * QKV_N];
__device__ int   g_cnt  [NEXP];
__device__ int   g_tok  [NEXP * BATCH];
__device__ int   g_slot [NEXP * BATCH];
__device__ float g_wt   [NEXP * BATCH];
__device__ float g_pm [BATCH * NKV * NCHUNK * GQA];
__device__ float g_pl [BATCH * NKV * NCHUNK * GQA];
__device__ float g_po [BATCH * NKV * NCHUNK * GQA * HD];
// bf16 split activations
__device__ __nv_bfloat16 g_hnh [BATCH * HDIM];
__device__ __nv_bfloat16 g_hnl [BATCH * HDIM];
__device__ __nv_bfloat16 g_ath [BATCH * NH * HD];
__device__ __nv_bfloat16 g_atl [BATCH * NH * HD];
__device__ __nv_bfloat16 g_h2h [BATCH * HDIM];
__device__ __nv_bfloat16 g_h2l [BATCH * HDIM];
__device__ __nv_bfloat16 g_acth[NEXP * BATCH * IDIM];
__device__ __nv_bfloat16 g_actl[NEXP * BATCH * IDIM];

// ---------------- helpers ----------------
__device__ __forceinline__ void split1(float f, __nv_bfloat16& h, __nv_bfloat16& l) {
    h = __float2bfloat16(f);
    l = __float2bfloat16(f - __bfloat162float(h));
}
__device__ __forceinline__ unsigned pk2(__nv_bfloat16 a, __nv_bfloat16 b) {
    __nv_bfloat162 h; h.x = a; h.y = b;
    return *reinterpret_cast<unsigned*>(&h);
}
// packed split: {f0,f1} -> hi pair (bf16x2) + lo pair (bf16x2); lo in low half.
__device__ __forceinline__ void split2(float f0, float f1, unsigned& hp, unsigned& lp) {
    unsigned h;
    asm("cvt.rn.bf16x2.f32 %0, %1, %2;" : "=r"(h) : "f"(f1), "f"(f0));
    float h0 = __uint_as_float(h << 16);
    float h1 = __uint_as_float(h & 0xffff0000u);
    float l0 = f0 - h0, l1 = f1 - h1;
    unsigned l;
    asm("cvt.rn.bf16x2.f32 %0, %1, %2;" : "=r"(l) : "f"(l1), "f"(l0));
    hp = h; lp = l;
}
__device__ __forceinline__ void mma16816(
    float& c0, float& c1, float& c2, float& c3,
    unsigned a0, unsigned a1, unsigned a2, unsigned a3,
    unsigned b0, unsigned b1)
{
    asm volatile(
        "mma.sync.aligned.m16n8k16.row.col.f32.bf16.bf16.f32 "
        "{%0,%1,%2,%3},{%4,%5,%6,%7},{%8,%9},{%0,%1,%2,%3};"
        : "+f"(c0), "+f"(c1), "+f"(c2), "+f"(c3)
        : "r"(a0), "r"(a1), "r"(a2), "r"(a3), "r"(b0), "r"(b1));
}

// ---------------- reset ----------------
__global__ void reset_k() {
    if (threadIdx.x < NEXP) g_cnt[threadIdx.x] = 0;
}

// ---------------- RMSNorm: fp32 + bf16 split out ----------------
__global__ __launch_bounds__(256) void rmsnorm_k(
    const float* __restrict__ x, const float* __restrict__ w,
    float* __restrict__ y, __nv_bfloat16* __restrict__ yh, __nv_bfloat16* __restrict__ yl)
{
    int b = blockIdx.x, tid = threadIdx.x;
    const float* xb = x + b * HDIM;
    float s = 0.f;
    for (int i = tid; i < HDIM; i += 256) { float v = xb[i]; s += v * v; }
    for (int o = 16; o; o >>= 1) s += __shfl_xor_sync(0xffffffffu, s, o);
    __shared__ float red[8];
    __shared__ float inv;
    if ((tid & 31) == 0) red[tid >> 5] = s;
    __syncthreads();
    if (tid == 0) {
        float t = 0.f;
        #pragma unroll
        for (int i = 0; i < 8; i++) t += red[i];
        inv = rsqrtf(t * (1.f / HDIM) + EPS);
    }
    __syncthreads();
    float iv = inv;
    for (int i = tid; i < HDIM; i += 256) {
        float v = xb[i] * iv * w[i];
        y[b * HDIM + i] = v;
        __nv_bfloat16 h, l; split1(v, h, l);
        yh[b * HDIM + i] = h; yl[b * HDIM + i] = l;
    }
}

// ---------------- tensor GEMM partial (bf16x3) ----------------
__global__ __launch_bounds__(256) void gemm_part_tc(
    const __nv_bfloat16* __restrict__ Ah, const __nv_bfloat16* __restrict__ Al,
    const float* __restrict__ W, float* __restrict__ part, int N, int K, int ksplit)
{
    __shared__ __nv_bfloat16 sAh[2][64][40], sAl[2][64][40];
    __shared__ __nv_bfloat16 sWh[2][64][40], sWl[2][64][40];
    int nb = blockIdx.x * 64;
    int ks = blockIdx.y;
    int klen = K / ksplit, kbeg = ks * klen, tiles = klen / 32;
    int tid = threadIdx.x, lane = tid & 31, warp = tid >> 5;
    int mw = warp & 3, nw = warp >> 2;
    int gr = lane >> 2, tc = lane & 3;

    int lm = tid >> 2, lk8 = (tid & 3) * 8;
    const __nv_bfloat16* Agh = Ah + (long)lm * K + kbeg + lk8;
    const __nv_bfloat16* Agl = Al + (long)lm * K + kbeg + lk8;
    const float* Wg = W + (long)(nb + lm) * K + kbeg + lk8;

    float acc[4][4] = {};
    uint4 rah[2], ral[2];
    float4 rw[2][2];
    #pragma unroll
    for (int s = 0; s < 2; s++) {
        rah[s] = *(const uint4*)(Agh + s * 32);
        ral[s] = *(const uint4*)(Agl + s * 32);
        rw[s][0] = *(const float4*)(Wg + s * 32);
        rw[s][1] = *(const float4*)(Wg + s * 32 + 4);
    }

    for (int t = 0; t < tiles; t += 2) {
        #pragma unroll
        for (int p = 0; p < 2; p++) {
            *(uint4*)&sAh[p][lm][lk8] = rah[p];
            *(uint4*)&sAl[p][lm][lk8] = ral[p];
            {
                uint4 uh, ul;
                split2(rw[p][0].x, rw[p][0].y, uh.x, ul.x);
                split2(rw[p][0].z, rw[p][0].w, uh.y, ul.y);
                split2(rw[p][1].x, rw[p][1].y, uh.z, ul.z);
                split2(rw[p][1].z, rw[p][1].w, uh.w, ul.w);
                *(uint4*)&sWh[p][lm][lk8] = uh;
                *(uint4*)&sWl[p][lm][lk8] = ul;
            }
            if (t + p + 2 < tiles) {
                rah[p] = *(const uint4*)(Agh + (t + p + 2) * 32);
                ral[p] = *(const uint4*)(Agl + (t + p + 2) * 32);
                rw[p][0] = *(const float4*)(Wg + (t + p + 2) * 32);
                rw[p][1] = *(const float4*)(Wg + (t + p + 2) * 32 + 4);
            }
            __syncthreads();
            #pragma unroll
            for (int k16 = 0; k16 < 2; k16++) {
                int kc = k16 * 16 + tc * 2;
                int ra = mw * 16 + gr;
                unsigned ah0 = *(const unsigned*)&sAh[p][ra][kc];
                unsigned ah1 = *(const unsigned*)&sAh[p][ra + 8][kc];
                unsigned ah2 = *(const unsigned*)&sAh[p][ra][kc + 8];
                unsigned ah3 = *(const unsigned*)&sAh[p][ra + 8][kc + 8];
                unsigned al0 = *(const unsigned*)&sAl[p][ra][kc];
                unsigned al1 = *(const unsigned*)&sAl[p][ra + 8][kc];
                unsigned al2 = *(const unsigned*)&sAl[p][ra][kc + 8];
                unsigned al3 = *(const unsigned*)&sAl[p][ra + 8][kc + 8];
                #pragma unroll
                for (int j = 0; j < 4; j++) {
                    int n = nw * 32 + j * 8 + gr;
                    unsigned bh0 = *(const unsigned*)&sWh[p][n][kc];
                    unsigned bh1 = *(const unsigned*)&sWh[p][n][kc + 8];
                    unsigned bl0 = *(const unsigned*)&sWl[p][n][kc];
                    unsigned bl1 = *(const unsigned*)&sWl[p][n][kc + 8];
                    mma16816(acc[j][0], acc[j][1], acc[j][2], acc[j][3],
                             ah0, ah1, ah2, ah3, bh0, bh1);
                    mma16816(acc[j][0], acc[j][1], acc[j][2], acc[j][3],
                             ah0, ah1, ah2, ah3, bl0, bl1);
                    mma16816(acc[j][0], acc[j][1], acc[j][2], acc[j][3],
                             al0, al1, al2, al3, bh0, bh1);
                }
            }
            __syncthreads();
        }
    }

    #pragma unroll
    for (int j = 0; j < 4; j++) {
        int col = nb + nw * 32 + j * 8 + tc * 2;
        long r0 = (long)(ks * 64 + mw * 16 + gr) * N + col;
        *(float2*)&part[r0] = make_float2(acc[j][0], acc[j][1]);
        *(float2*)&part[r0 + 8L * N] = make_float2(acc[j][2], acc[j][3]);
    }
}

// ---------------- GEMM reduce ----------------
__global__ __launch_bounds__(256) void gemm_reduce_k(
    const float* __restrict__ part, const float* __restrict__ bias,
    const float* __restrict__ res, float* __restrict__ C, int N, int ksplit)
{
    int idx = (blockIdx.x * 256 + threadIdx.x) * 4;
    int m = idx / N, n = idx % N;
    float4 s = bias ? *(const float4*)&bias[n] : make_float4(0.f, 0.f, 0.f, 0.f);
    for (int ks = 0; ks < ksplit; ks++) {
        float4 p = *(const float4*)&part[((long)(ks * 64 + m)) * N + n];
        s.x += p.x; s.y += p.y; s.z += p.z; s.w += p.w;
    }
    if (res) {
        float4 r = *(const float4*)&res[idx];
        s.x += r.x; s.y += r.y; s.z += r.z; s.w += r.w;
    }
    *(float4*)&C[idx] = s;
}

// ---------------- split-S GQA flash-decode (scalar, proven) ----------------
__global__ __launch_bounds__(256) void attn_part_k(
    const float* __restrict__ kc, const float* __restrict__ vc,
    const int* __restrict__ seq_lens)
{
    int c  = blockIdx.x;
    int kv = blockIdx.y;
    int b  = blockIdx.z;
    int tid = threadIdx.x, warp = tid >> 5, lane = tid & 31;
    int sl = seq_lens[b];
    if (sl < 0) sl = 0;
    if (sl > SEQ - 1) sl = SEQ - 1;
    int L  = sl + 1;
    int s0 = c * SCHUNK;
    if (s0 >= L) return;
    int s1 = s0 + SCHUNK; if (s1 > L) s1 = L;
    const float scale = 0.08838834764831845f;

    const float* qbase = g_qkv + b * QKV_N + kv * GQA * HD;
    const float* knew  = g_qkv + b * QKV_N + NH * HD + kv * HD;
    const float* vnew  = g_qkv + b * QKV_N + (NH + NKV) * HD + kv * HD;

    float4 q[GQA];
    #pragma unroll
    for (int h = 0; h < GQA; h++) q[h] = *(const float4*)(qbase + h * HD + lane * 4);

    float m[GQA], l[GQA];
    float4 o[GQA];
    #pragma unroll
    for (int h = 0; h < GQA; h++) {
        m[h] = -INFINITY; l[h] = 0.f; o[h] = make_float4(0.f, 0.f, 0.f, 0.f);
    }

    int s = s0 + warp;
    if (s < s1) {
        const float* kp = (s == sl) ? knew : (kc + ((size_t)(b * SEQ + s) * NKV + kv) * HD);
        const float* vp = (s == sl) ? vnew : (vc + ((size_t)(b * SEQ + s) * NKV + kv) * HD);
        float4 kk = *(const float4*)(kp + lane * 4);
        float4 vv = *(const float4*)(vp + lane * 4);
        for (;;) {
            int sn = s + 8;
            float4 knx, vnx;
            if (sn < s1) {
                const float* kp2 = (sn == sl) ? knew : (kc + ((size_t)(b * SEQ + sn) * NKV + kv) * HD);
                const float* vp2 = (sn == sl) ? vnew : (vc + ((size_t)(b * SEQ + sn) * NKV + kv) * HD);
                knx = *(const float4*)(kp2 + lane * 4);
                vnx = *(const float4*)(vp2 + lane * 4);
            }
            #pragma unroll
            for (int h = 0; h < GQA; h++) {
                float d = q[h].x * kk.x + q[h].y * kk.y + q[h].z * kk.z + q[h].w * kk.w;
                d += __shfl_xor_sync(0xffffffffu, d, 16);
                d += __shfl_xor_sync(0xffffffffu, d, 8);
                d += __shfl_xor_sync(0xffffffffu, d, 4);
                d += __shfl_xor_sync(0xffffffffu, d, 2);
                d += __shfl_xor_sync(0xffffffffu, d, 1);
                float sc = d * scale;
                float nm = fmaxf(m[h], sc);
                float corr = __expf(m[h] - nm);
                float p = __expf(sc - nm);
                l[h] = l[h] * corr + p;
                o[h].x = o[h].x * corr + p * vv.x;
                o[h].y = o[h].y * corr + p * vv.y;
                o[h].z = o[h].z * corr + p * vv.z;
                o[h].w = o[h].w * corr + p * vv.w;
                m[h] = nm;
            }
            if (sn >= s1) break;
            s = sn; kk = knx; vv = vnx;
        }
    }

    __shared__ float sm[8][GQA], sll[8][GQA];
    __shared__ float so[8][GQA][HD];
    #pragma unroll
    for (int h = 0; h < GQA; h++) {
        if (lane == 0) { sm[warp][h] = m[h]; sll[warp][h] = l[h]; }
        *(float4*)&so[warp][h][lane * 4] = o[h];
    }
    __syncthreads();

    int pbase = ((b * NKV + kv) * NCHUNK + c) * GQA;
    for (int idx = tid; idx < GQA * HD; idx += 256) {
        int h = idx >> 7, d = idx & (HD - 1);
        float M = -INFINITY;
        #pragma unroll
        for (int w = 0; w < 8; w++) M = fmaxf(M, sm[w][h]);
        float acc = 0.f, Ls = 0.f;
        #pragma unroll
        for (int w = 0; w < 8; w++) {
            float cw = __expf(sm[w][h] - M);
            acc += cw * so[w][h][d];
            Ls  += cw * sll[w][h];
        }
        g_po[(pbase + h) * HD + d] = acc;
        if (d == 0) { g_pm[pbase + h] = M; g_pl[pbase + h] = Ls; }
    }
}

// ---------------- combine split-S partials -> bf16 split ----------------
__global__ __launch_bounds__(256) void attn_comb_k(
    const int* __restrict__ seq_lens,
    __nv_bfloat16* __restrict__ outh, __nv_bfloat16* __restrict__ outl)
{
    int b  = blockIdx.x >> 2;
    int kv = blockIdx.x & 3;
    int tid = threadIdx.x;
    int sl = seq_lens[b];
    if (sl < 0) sl = 0;
    if (sl > SEQ - 1) sl = SEQ - 1;
    int nch = sl / SCHUNK + 1;
    int base = (b * NKV + kv) * NCHUNK;

    for (int idx = tid; idx < GQA * HD; idx += 256) {
        int h = idx >> 7, d = idx & (HD - 1);
        float M = -INFINITY;
        for (int c = 0; c < nch; c++) M = fmaxf(M, g_pm[(base + c) * GQA + h]);
        float acc = 0.f, Ls = 0.f;
        for (int c = 0; c < nch; c++) {
            float w = __expf(g_pm[(base + c) * GQA + h] - M);
            acc += w * g_po[((base + c) * GQA + h) * HD + d];
            Ls  += w * g_pl[(base + c) * GQA + h];
        }
        float v = acc / Ls;
        __nv_bfloat16 hh, ll; split1(v, hh, ll);
        long o = (long)b * NH * HD + (kv * GQA + h) * HD + d;
        outh[o] = hh; outl[o] = ll;
    }
}

// ---------------- gate ----------------
__global__ __launch_bounds__(256) void gate_k(const float* __restrict__ gw)
{
    int b = blockIdx.x, tid = threadIdx.x, warp = tid >> 5, lane = tid & 31;
    __shared__ float lg[NEXP];
    const float* h = g_h2 + b * HDIM;
    for (int e = warp; e < NEXP; e += 8) {
        const float* g = gw + e * HDIM;
        float s = 0.f;
        for (int i = lane; i < HDIM; i += 32) s += h[i] * g[i];
        for (int o = 16; o; o >>= 1) s += __shfl_xor_sync(0xffffffffu, s, o);
        if (lane == 0) lg[e] = s;
    }
    __syncthreads();
    if (tid == 0) {
        float val[TOPK]; int idx[TOPK];
        unsigned used = 0;
        for (int j = 0; j < TOPK; j++) {
            float best = -1e30f; int bi = 0;
            for (int e = 0; e < NEXP; e++)
                if (!((used >> e) & 1u) && lg[e] > best) { best = lg[e]; bi = e; }
            used |= 1u << bi; val[j] = best; idx[j] = bi;
        }
        float s = 0.f, wj[TOPK];
        for (int j = 0; j < TOPK; j++) { wj[j] = expf(val[j] - val[0]); s += wj[j]; }
        float is = 1.f / s;
        for (int j = 0; j < TOPK; j++) {
            int e = idx[j];
            int pos = atomicAdd(&g_cnt[e], 1);
            g_tok [e * BATCH + pos] = b;
            g_slot[e * BATCH + pos] = j;
            g_wt  [e * BATCH + pos] = wj[j] * is;
        }
    }
}

// ---------------- MoE w1 (tensor, bf16x3, fused SwiGLU) ----------------
__global__ __launch_bounds__(256) void moe_w1_tc(const float* __restrict__ w1)
{
    int e = blockIdx.y;
    int cnt = g_cnt[e];
    int m0 = blockIdx.z * 16;
    if (m0 >= cnt) return;
    int ib = blockIdx.x * 64;

    __shared__ __align__(16) char SM[46080];
    __nv_bfloat16* pAh = (__nv_bfloat16*)SM;
    __nv_bfloat16* pAl = pAh + 1280;
    __nv_bfloat16* pWh = pAl + 1280;
    __nv_bfloat16* pWl = pWh + 10240;
    float* Csm = (float*)SM;
    __shared__ int toks[16];

    int tid = threadIdx.x, lane = tid & 31, warp = tid >> 5;
    int gr = lane >> 2, tc = lane & 3;
    if (tid < 16) toks[tid] = (m0 + tid < cnt) ? g_tok[e * BATCH + m0 + tid]
                                               : g_tok[e * BATCH];
    __syncthreads();

    int ar = tid >> 4, akp = (tid & 15) * 2;
    const __nv_bfloat16* Agh = g_h2h + (long)toks[ar] * HDIM + akp;
    const __nv_bfloat16* Agl = g_h2l + (long)toks[ar] * HDIM + akp;
    int lw = tid >> 1, wk = (tid & 1) * 16;
    long wrow = (long)e * 2 * IDIM + ((lw < 64) ? (ib + lw) : (IDIM + ib + lw - 64));
    const float* Wg = w1 + wrow * HDIM + wk;

    const int tiles = HDIM / 32;
    float acc[2][4] = {};

    unsigned rah[2], ral[2];
    float4 rw[2][4];
    #pragma unroll
    for (int s = 0; s < 2; s++) {
        rah[s] = *(const unsigned*)(Agh + s * 32);
        ral[s] = *(const unsigned*)(Agl + s * 32);
        #pragma unroll
        for (int q = 0; q < 4; q++) rw[s][q] = *(const float4*)(Wg + s * 32 + q * 4);
    }

    for (int t = 0; t < tiles; t += 2) {
        #pragma unroll
        for (int p = 0; p < 2; p++) {
            *(unsigned*)&pAh[p * 640 + ar * 40 + akp] = rah[p];
            *(unsigned*)&pAl[p * 640 + ar * 40 + akp] = ral[p];
            {
                uint4 uh0, uh1, ul0, ul1;
                split2(rw[p][0].x, rw[p][0].y, uh0.x, ul0.x);
                split2(rw[p][0].z, rw[p][0].w, uh0.y, ul0.y);
                split2(rw[p][1].x, rw[p][1].y, uh0.z, ul0.z);
                split2(rw[p][1].z, rw[p][1].w, uh0.w, ul0.w);
                split2(rw[p][2].x, rw[p][2].y, uh1.x, ul1.x);
                split2(rw[p][2].z, rw[p][2].w, uh1.y, ul1.y);
                split2(rw[p][3].x, rw[p][3].y, uh1.z, ul1.z);
                split2(rw[p][3].z, rw[p][3].w, uh1.w, ul1.w);
                long o = p * 5120 + lw * 40 + wk;
                *(uint4*)&pWh[o] = uh0; *(uint4*)&pWh[o + 8] = uh1;
                *(uint4*)&pWl[o] = ul0; *(uint4*)&pWl[o + 8] = ul1;
            }
            if (t + p + 2 < tiles) {
                rah[p] = *(const unsigned*)(Agh + (t + p + 2) * 32);
                ral[p] = *(const unsigned*)(Agl + (t + p + 2) * 32);
                #pragma unroll
                for (int q = 0; q < 4; q++)
                    rw[p][q] = *(const float4*)(Wg + (t + p + 2) * 32 + q * 4);
            }
            __syncthreads();
            #pragma unroll
            for (int k16 = 0; k16 < 2; k16++) {
                int kc = k16 * 16 + tc * 2;
                unsigned ah0 = *(const unsigned*)&pAh[p * 640 + gr * 40 + kc];
                unsigned ah1 = *(const unsigned*)&pAh[p * 640 + (gr + 8) * 40 + kc];
                unsigned ah2 = *(const unsigned*)&pAh[p * 640 + gr * 40 + kc + 8];
                unsigned ah3 = *(const unsigned*)&pAh[p * 640 + (gr + 8) * 40 + kc + 8];
                unsigned al0 = *(const unsigned*)&pAl[p * 640 + gr * 40 + kc];
                unsigned al1 = *(const unsigned*)&pAl[p * 640 + (gr + 8) * 40 + kc];
                unsigned al2 = *(const unsigned*)&pAl[p * 640 + gr * 40 + kc + 8];
                unsigned al3 = *(const unsigned*)&pAl[p * 640 + (gr + 8) * 40 + kc + 8];
                #pragma unroll
                for (int j = 0; j < 2; j++) {
                    int n = warp * 16 + j * 8 + gr;
                    unsigned bh0 = *(const unsigned*)&pWh[p * 5120 + n * 40 + kc];
                    unsigned bh1 = *(const unsigned*)&pWh[p * 5120 + n * 40 + kc + 8];
                    unsigned bl0 = *(const unsigned*)&pWl[p * 5120 + n * 40 + kc];
                    unsigned bl1 = *(const unsigned*)&pWl[p * 5120 + n * 40 + kc + 8];
                    mma16816(acc[j][0], acc[j][1], acc[j][2], acc[j][3],
                             ah0, ah1, ah2, ah3, bh0, bh1);
                    mma16816(acc[j][0], acc[j][1], acc[j][2], acc[j][3],
                             ah0, ah1, ah2, ah3, bl0, bl1);
                    mma16816(acc[j][0], acc[j][1], acc[j][2], acc[j][3],
                             al0, al1, al2, al3, bh0, bh1);
                }
            }
            __syncthreads();
        }
    }

    #pragma unroll
    for (int j = 0; j < 2; j++) {
        int col = warp * 16 + j * 8 + tc * 2;
        Csm[gr * 132 + col] = acc[j][0];
        Csm[gr * 132 + col + 1] = acc[j][1];
        Csm[(gr + 8) * 132 + col] = acc[j][2];
        Csm[(gr + 8) * 132 + col + 1] = acc[j][3];
    }
    __syncthreads();

    #pragma unroll
    for (int it = 0; it < 4; it++) {
        int idx = tid + it * 256;
        int m = idx >> 6, n = idx & 63;
        if (m0 + m < cnt) {
            float gg = Csm[m * 132 + n];
            float uu = Csm[m * 132 + 64 + n];
            float a = gg / (1.f + expf(-gg)) * uu;
            __nv_bfloat16 h, l; split1(a, h, l);
            long o = (long)(e * BATCH + m0 + m) * IDIM + ib + n;
            g_acth[o] = h; g_actl[o] = l;
        }
    }
}

// ---------------- MoE w2 (tensor, bf16x3, weighted scatter) ----------------
__global__ __launch_bounds__(128) void moe_w2_tc(const float* __restrict__ w2)
{
    int e = blockIdx.y;
    int cnt = g_cnt[e];
    int m0 = blockIdx.z * 16;
    if (m0 >= cnt) return;
    int hb = blockIdx.x * 64;

    __shared__ __nv_bfloat16 sAh[2][16][40], sAl[2][16][40];
    __shared__ __nv_bfloat16 sWh[2][64][40], sWl[2][64][40];

    int tid = threadIdx.x, lane = tid & 31, warp = tid >> 5;
    int gr = lane >> 2, tc = lane & 3;

    int ar = tid >> 3, akp = (tid & 7) * 4;
    const __nv_bfloat16* Agh = g_acth + (long)(e * BATCH + m0 + ar) * IDIM + akp;
    const __nv_bfloat16* Agl = g_actl + (long)(e * BATCH + m0 + ar) * IDIM + akp;
    int lw = tid >> 1, wk = (tid & 1) * 16;
    const float* Wg = w2 + ((long)e * HDIM + hb + lw) * IDIM + wk;

    const int tiles = IDIM / 32;
    float acc[2][4] = {};

    uint2 rah[2], ral[2];
    float4 rw[2][4];
    #pragma unroll
    for (int s = 0; s < 2; s++) {
        rah[s] = *(const uint2*)(Agh + s * 32);
        ral[s] = *(const uint2*)(Agl + s * 32);
        #pragma unroll
        for (int q = 0; q < 4; q++) rw[s][q] = *(const float4*)(Wg + s * 32 + q * 4);
    }

    for (int t = 0; t < tiles; t += 2) {
        #pragma unroll
        for (int p = 0; p < 2; p++) {
            *(uint2*)&sAh[p][ar][akp] = rah[p];
            *(uint2*)&sAl[p][ar][akp] = ral[p];
            {
                uint4 uh0, uh1, ul0, ul1;
                split2(rw[p][0].x, rw[p][0].y, uh0.x, ul0.x);
                split2(rw[p][0].z, rw[p][0].w, uh0.y, ul0.y);
                split2(rw[p][1].x, rw[p][1].y, uh0.z, ul0.z);
                split2(rw[p][1].z, rw[p][1].w, uh0.w, ul0.w);
                split2(rw[p][2].x, rw[p][2].y, uh1.x, ul1.x);
                split2(rw[p][2].z, rw[p][2].w, uh1.y, ul1.y);
                split2(rw[p][3].x, rw[p][3].y, uh1.z, ul1.z);
                split2(rw[p][3].z, rw[p][3].w, uh1.w, ul1.w);
                *(uint4*)&sWh[p][lw][wk] = uh0; *(uint4*)&sWh[p][lw][wk + 8] = uh1;
                *(uint4*)&sWl[p][lw][wk] = ul0; *(uint4*)&sWl[p][lw][wk + 8] = ul1;
            }
            if (t + p + 2 < tiles) {
                rah[p] = *(const uint2*)(Agh + (t + p + 2) * 32);
                ral[p] = *(const uint2*)(Agl + (t + p + 2) * 32);
                #pragma unroll
                for (int q = 0; q < 4; q++)
                    rw[p][q] = *(const float4*)(Wg + (t + p + 2) * 32 + q * 4);
            }
            __syncthreads();
            #pragma unroll
            for (int k16 = 0; k16 < 2; k16++) {
                int kc = k16 * 16 + tc * 2;
                unsigned ah0 = *(const unsigned*)&sAh[p][gr][kc];
                unsigned ah1 = *(const unsigned*)&sAh[p][gr + 8][kc];
                unsigned ah2 = *(const unsigned*)&sAh[p][gr][kc + 8];
                unsigned ah3 = *(const unsigned*)&sAh[p][gr + 8][kc + 8];
                unsigned al0 = *(const unsigned*)&sAl[p][gr][kc];
                unsigned al1 = *(const unsigned*)&sAl[p][gr + 8][kc];
                unsigned al2 = *(const unsigned*)&sAl[p][gr][kc + 8];
                unsigned al3 = *(const unsigned*)&sAl[p][gr + 8][kc + 8];
                #pragma unroll
                for (int j = 0; j < 2; j++) {
                    int n = warp * 16 + j * 8 + gr;
                    unsigned bh0 = *(const unsigned*)&sWh[p][n][kc];
                    unsigned bh1 = *(const unsigned*)&sWh[p][n][kc + 8];
                    unsigned bl0 = *(const unsigned*)&sWl[p][n][kc];
                    unsigned bl1 = *(const unsigned*)&sWl[p][n][kc + 8];
                    mma16816(acc[j][0], acc[j][1], acc[j][2], acc[j][3],
                             ah0, ah1, ah2, ah3, bh0, bh1);
                    mma16816(acc[j][0], acc[j][1], acc[j][2], acc[j][3],
                             ah0, ah1, ah2, ah3, bl0, bl1);
                    mma16816(acc[j][0], acc[j][1], acc[j][2], acc[j][3],
                             al0, al1, al2, al3, bh0, bh1);
                }
            }
            __syncthreads();
        }
    }

    #pragma unroll
    for (int j = 0; j < 2; j++) {
        int col = hb + warp * 16 + j * 8 + tc * 2;
        int m1 = m0 + gr, m2 = m0 + gr + 8;
        if (m1 < cnt) {
            int tok = g_tok[e * BATCH + m1], sj = g_slot[e * BATCH + m1];
            float w = g_wt[e * BATCH + m1];
            float* yp = &g_ypair[(long)(tok * TOPK + sj) * HDIM + col];
            yp[0] = w * acc[j][0]; yp[1] = w * acc[j][1];
        }
        if (m2 < cnt) {
            int tok = g_tok[e * BATCH + m2], sj = g_slot[e * BATCH + m2];
            float w = g_wt[e * BATCH + m2];
            float* yp = &g_ypair[(long)(tok * TOPK + sj) * HDIM + col];
            yp[0] = w * acc[j][2]; yp[1] = w * acc[j][3];
        }
    }
}

// ---------------- finalize ----------------
__global__ __launch_bounds__(256) void finalize_k(float* __restrict__ out)
{
    int idx = blockIdx.x * 256 + threadIdx.x;
    int tok = idx >> 11, hh = idx & (HDIM - 1);
    float s = g_hs2[idx];
    #pragma unroll
    for (int j = 0; j < TOPK; j++) s += g_ypair[(tok * TOPK + j) * HDIM + hh];
    out[idx] = s;
}

// ---------------- launch ----------------
extern "C" void kernel_launch(void* const* d_in, const int* in_sizes, int n_in,
                              void* d_out, int out_size)
{
    static float *p_hn = 0, *p_qkv = 0, *p_hs2 = 0, *p_h2 = 0, *p_part = 0;
    static __nv_bfloat16 *p_hnh = 0, *p_hnl = 0, *p_ath = 0, *p_atl = 0, *p_h2h = 0, *p_h2l = 0;
    if (!p_hn) {
        cudaGetSymbolAddress((void**)&p_hn,   g_hn);
        cudaGetSymbolAddress((void**)&p_qkv,  g_qkv);
        cudaGetSymbolAddress((void**)&p_hs2,  g_hs2);
        cudaGetSymbolAddress((void**)&p_h2,   g_h2);
        cudaGetSymbolAddress((void**)&p_part, g_part);
        cudaGetSymbolAddress((void**)&p_hnh,  g_hnh);
        cudaGetSymbolAddress((void**)&p_hnl,  g_hnl);
        cudaGetSymbolAddress((void**)&p_ath,  g_ath);
        cudaGetSymbolAddress((void**)&p_atl,  g_atl);
        cudaGetSymbolAddress((void**)&p_h2h,  g_h2h);
        cudaGetSymbolAddress((void**)&p_h2l,  g_h2l);
    }

    const float *hidden = 0, *k_cache = 0, *v_cache = 0, *w_qkv = 0, *b_qkv = 0;
    const float *w_o = 0, *ln1_w = 0, *ln2_w = 0, *gate_w = 0, *w1 = 0, *w2 = 0;
    const int *positions = 0, *seqlens = 0;

    for (int i = 0; i < n_in; i++) {
        long sz = (long)in_sizes[i];
        const void* p = d_in[i];
        if      (sz == (long)BATCH * HDIM)            hidden = (const float*)p;
        else if (sz == (long)BATCH) {
            if (!positions) positions = (const int*)p; else seqlens = (const int*)p;
        }
        else if (sz == (long)BATCH * SEQ * NKV * HD) {
            if (!k_cache) k_cache = (const float*)p; else v_cache = (const float*)p;
        }
        else if (sz == (long)QKV_N * HDIM)            w_qkv  = (const float*)p;
        else if (sz == (long)QKV_N)                   b_qkv  = (const float*)p;
        else if (sz == (long)HDIM * NH * HD)          w_o    = (const float*)p;
        else if (sz == (long)HDIM) {
            if (!ln1_w) ln1_w = (const float*)p; else ln2_w = (const float*)p;
        }
        else if (sz == (long)NEXP * HDIM)             gate_w = (const float*)p;
        else if (sz == (long)NEXP * 2 * IDIM * HDIM)  w1     = (const float*)p;
        else if (sz == (long)NEXP * HDIM * IDIM)      w2     = (const float*)p;
    }
    if (!seqlens && positions) seqlens = positions;
    if (!v_cache) v_cache = k_cache;
    if (!ln2_w)   ln2_w   = ln1_w;

    float* out = (float*)d_out;

    reset_k<<<1, 32>>>();
    rmsnorm_k<<<BATCH, 256>>>(hidden, ln1_w, p_hn, p_hnh, p_hnl);
    gemm_part_tc<<<dim3(QKV_N / 64, 4), 256>>>(p_hnh, p_hnl, w_qkv, p_part, QKV_N, HDIM, 4);
    gemm_reduce_k<<<(64 * QKV_N) / 1024, 256>>>(p_part, b_qkv, nullptr, p_qkv, QKV_N, 4);
    attn_part_k<<<dim3(NCHUNK, NKV, BATCH), 256>>>(k_cache, v_cache, seqlens);
    attn_comb_k<<<BATCH * NKV, 256>>>(seqlens, p_ath, p_atl);
    gemm_part_tc<<<dim3(HDIM / 64, 8), 256>>>(p_ath, p_atl, w_o, p_part, HDIM, NH * HD, 8);
    gemm_reduce_k<<<(64 * HDIM) / 1024, 256>>>(p_part, nullptr, hidden, p_hs2, HDIM, 8);
    rmsnorm_k<<<BATCH, 256>>>(p_hs2, ln2_w, p_h2, p_h2h, p_h2l);
    gate_k<<<BATCH, 256>>>(gate_w);
    moe_w1_tc<<<dim3(IDIM / 64, NEXP, 4), 256>>>(w1);
    moe_w2_tc<<<dim3(HDIM / 64, NEXP, 4), 128>>>(w2);
    finalize_k<<<(BATCH * HDIM) / 256, 256>>>(out);
}

// round 17
// speedup vs baseline: 1.1200x; 1.0110x over previous
#include <cuda_runtime.h>
#include <cuda_bf16.h>
#include <math.h>

// ---------------- problem constants ----------------
#define BATCH 64
#define HDIM  2048
#define SEQ   2048
#define NH    32
#define NKV   4
#define GQA   8
#define HD    128
#define NEXP  32
#define IDIM  768
#define TOPK  4
#define QKV_N 5120
#define EPS   1e-6f
#define SCHUNK 256
#define NCHUNK (SEQ / SCHUNK)

// ---------------- scratch (device globals) ----------------
// args must come from cudaGetSymbolAddress (ATS host-shadow bug, rounds 1-5).
__device__ float g_hn   [BATCH * HDIM];
__device__ float g_qkv  [BATCH * QKV_N];
__device__ float g_hs2  [BATCH * HDIM];
__device__ float g_h2   [BATCH * HDIM];
__device__ float g_ypair[BATCH * TOPK * HDIM];
__device__ float g_part [4 * BATCH * QKV_N];
__device__ int   g_cnt  [NEXP];
__device__ int   g_tok  [NEXP * BATCH];
__device__ int   g_slot [NEXP * BATCH];
__device__ float g_wt   [NEXP * BATCH];
__device__ float g_pm [BATCH * NKV * NCHUNK * GQA];
__device__ float g_pl [BATCH * NKV * NCHUNK * GQA];
__device__ float g_po [BATCH * NKV * NCHUNK * GQA * HD];
// bf16 split activations
__device__ __nv_bfloat16 g_hnh [BATCH * HDIM];
__device__ __nv_bfloat16 g_hnl [BATCH * HDIM];
__device__ __nv_bfloat16 g_ath [BATCH * NH * HD];
__device__ __nv_bfloat16 g_atl [BATCH * NH * HD];
__device__ __nv_bfloat16 g_h2h [BATCH * HDIM];
__device__ __nv_bfloat16 g_h2l [BATCH * HDIM];
__device__ __nv_bfloat16 g_acth[NEXP * BATCH * IDIM];
__device__ __nv_bfloat16 g_actl[NEXP * BATCH * IDIM];

// ---------------- helpers ----------------
__device__ __forceinline__ void split1(float f, __nv_bfloat16& h, __nv_bfloat16& l) {
    h = __float2bfloat16(f);
    l = __float2bfloat16(f - __bfloat162float(h));
}
__device__ __forceinline__ unsigned pk2(__nv_bfloat16 a, __nv_bfloat16 b) {
    __nv_bfloat162 h; h.x = a; h.y = b;
    return *reinterpret_cast<unsigned*>(&h);
}
// packed split: {f0,f1} -> hi pair (bf16x2) + lo pair (bf16x2).
__device__ __forceinline__ void split2(float f0, float f1, unsigned& hp, unsigned& lp) {
    unsigned h;
    asm("cvt.rn.bf16x2.f32 %0, %1, %2;" : "=r"(h) : "f"(f1), "f"(f0));
    float h0 = __uint_as_float(h << 16);
    float h1 = __uint_as_float(h & 0xffff0000u);
    float l0 = f0 - h0, l1 = f1 - h1;
    unsigned l;
    asm("cvt.rn.bf16x2.f32 %0, %1, %2;" : "=r"(l) : "f"(l1), "f"(l0));
    hp = h; lp = l;
}
__device__ __forceinline__ void mma16816(
    float& c0, float& c1, float& c2, float& c3,
    unsigned a0, unsigned a1, unsigned a2, unsigned a3,
    unsigned b0, unsigned b1)
{
    asm volatile(
        "mma.sync.aligned.m16n8k16.row.col.f32.bf16.bf16.f32 "
        "{%0,%1,%2,%3},{%4,%5,%6,%7},{%8,%9},{%0,%1,%2,%3};"
        : "+f"(c0), "+f"(c1), "+f"(c2), "+f"(c3)
        : "r"(a0), "r"(a1), "r"(a2), "r"(a3), "r"(b0), "r"(b1));
}

// ---------------- reset ----------------
__global__ void reset_k() {
    if (threadIdx.x < NEXP) g_cnt[threadIdx.x] = 0;
}

// ---------------- RMSNorm: fp32 + bf16 split out ----------------
__global__ __launch_bounds__(256) void rmsnorm_k(
    const float* __restrict__ x, const float* __restrict__ w,
    float* __restrict__ y, __nv_bfloat16* __restrict__ yh, __nv_bfloat16* __restrict__ yl)
{
    int b = blockIdx.x, tid = threadIdx.x;
    const float* xb = x + b * HDIM;
    float s = 0.f;
    for (int i = tid; i < HDIM; i += 256) { float v = xb[i]; s += v * v; }
    for (int o = 16; o; o >>= 1) s += __shfl_xor_sync(0xffffffffu, s, o);
    __shared__ float red[8];
    __shared__ float inv;
    if ((tid & 31) == 0) red[tid >> 5] = s;
    __syncthreads();
    if (tid == 0) {
        float t = 0.f;
        #pragma unroll
        for (int i = 0; i < 8; i++) t += red[i];
        inv = rsqrtf(t * (1.f / HDIM) + EPS);
    }
    __syncthreads();
    float iv = inv;
    for (int i = tid; i < HDIM; i += 256) {
        float v = xb[i] * iv * w[i];
        y[b * HDIM + i] = v;
        __nv_bfloat16 h, l; split1(v, h, l);
        yh[b * HDIM + i] = h; yl[b * HDIM + i] = l;
    }
}

// ---------------- tensor GEMM partial (bf16x3) ----------------
__global__ __launch_bounds__(256) void gemm_part_tc(
    const __nv_bfloat16* __restrict__ Ah, const __nv_bfloat16* __restrict__ Al,
    const float* __restrict__ W, float* __restrict__ part, int N, int K, int ksplit)
{
    __shared__ __nv_bfloat16 sAh[2][64][40], sAl[2][64][40];
    __shared__ __nv_bfloat16 sWh[2][64][40], sWl[2][64][40];
    int nb = blockIdx.x * 64;
    int ks = blockIdx.y;
    int klen = K / ksplit, kbeg = ks * klen, tiles = klen / 32;
    int tid = threadIdx.x, lane = tid & 31, warp = tid >> 5;
    int mw = warp & 3, nw = warp >> 2;
    int gr = lane >> 2, tc = lane & 3;

    int lm = tid >> 2, lk8 = (tid & 3) * 8;
    const __nv_bfloat16* Agh = Ah + (long)lm * K + kbeg + lk8;
    const __nv_bfloat16* Agl = Al + (long)lm * K + kbeg + lk8;
    const float* Wg = W + (long)(nb + lm) * K + kbeg + lk8;

    float acc[4][4] = {};
    uint4 rah[2], ral[2];
    float4 rw[2][2];
    #pragma unroll
    for (int s = 0; s < 2; s++) {
        rah[s] = *(const uint4*)(Agh + s * 32);
        ral[s] = *(const uint4*)(Agl + s * 32);
        rw[s][0] = *(const float4*)(Wg + s * 32);
        rw[s][1] = *(const float4*)(Wg + s * 32 + 4);
    }

    for (int t = 0; t < tiles; t += 2) {
        #pragma unroll
        for (int p = 0; p < 2; p++) {
            *(uint4*)&sAh[p][lm][lk8] = rah[p];
            *(uint4*)&sAl[p][lm][lk8] = ral[p];
            {
                uint4 uh, ul;
                split2(rw[p][0].x, rw[p][0].y, uh.x, ul.x);
                split2(rw[p][0].z, rw[p][0].w, uh.y, ul.y);
                split2(rw[p][1].x, rw[p][1].y, uh.z, ul.z);
                split2(rw[p][1].z, rw[p][1].w, uh.w, ul.w);
                *(uint4*)&sWh[p][lm][lk8] = uh;
                *(uint4*)&sWl[p][lm][lk8] = ul;
            }
            if (t + p + 2 < tiles) {
                rah[p] = *(const uint4*)(Agh + (t + p + 2) * 32);
                ral[p] = *(const uint4*)(Agl + (t + p + 2) * 32);
                rw[p][0] = *(const float4*)(Wg + (t + p + 2) * 32);
                rw[p][1] = *(const float4*)(Wg + (t + p + 2) * 32 + 4);
            }
            __syncthreads();
            #pragma unroll
            for (int k16 = 0; k16 < 2; k16++) {
                int kc = k16 * 16 + tc * 2;
                int ra = mw * 16 + gr;
                unsigned ah0 = *(const unsigned*)&sAh[p][ra][kc];
                unsigned ah1 = *(const unsigned*)&sAh[p][ra + 8][kc];
                unsigned ah2 = *(const unsigned*)&sAh[p][ra][kc + 8];
                unsigned ah3 = *(const unsigned*)&sAh[p][ra + 8][kc + 8];
                unsigned al0 = *(const unsigned*)&sAl[p][ra][kc];
                unsigned al1 = *(const unsigned*)&sAl[p][ra + 8][kc];
                unsigned al2 = *(const unsigned*)&sAl[p][ra][kc + 8];
                unsigned al3 = *(const unsigned*)&sAl[p][ra + 8][kc + 8];
                #pragma unroll
                for (int j = 0; j < 4; j++) {
                    int n = nw * 32 + j * 8 + gr;
                    unsigned bh0 = *(const unsigned*)&sWh[p][n][kc];
                    unsigned bh1 = *(const unsigned*)&sWh[p][n][kc + 8];
                    unsigned bl0 = *(const unsigned*)&sWl[p][n][kc];
                    unsigned bl1 = *(const unsigned*)&sWl[p][n][kc + 8];
                    mma16816(acc[j][0], acc[j][1], acc[j][2], acc[j][3],
                             ah0, ah1, ah2, ah3, bh0, bh1);
                    mma16816(acc[j][0], acc[j][1], acc[j][2], acc[j][3],
                             ah0, ah1, ah2, ah3, bl0, bl1);
                    mma16816(acc[j][0], acc[j][1], acc[j][2], acc[j][3],
                             al0, al1, al2, al3, bh0, bh1);
                }
            }
            __syncthreads();
        }
    }

    #pragma unroll
    for (int j = 0; j < 4; j++) {
        int col = nb + nw * 32 + j * 8 + tc * 2;
        long r0 = (long)(ks * 64 + mw * 16 + gr) * N + col;
        *(float2*)&part[r0] = make_float2(acc[j][0], acc[j][1]);
        *(float2*)&part[r0 + 8L * N] = make_float2(acc[j][2], acc[j][3]);
    }
}

// ---------------- GEMM reduce ----------------
__global__ __launch_bounds__(256) void gemm_reduce_k(
    const float* __restrict__ part, const float* __restrict__ bias,
    const float* __restrict__ res, float* __restrict__ C, int N, int ksplit)
{
    int idx = (blockIdx.x * 256 + threadIdx.x) * 4;
    int m = idx / N, n = idx % N;
    float4 s = bias ? *(const float4*)&bias[n] : make_float4(0.f, 0.f, 0.f, 0.f);
    for (int ks = 0; ks < ksplit; ks++) {
        float4 p = *(const float4*)&part[((long)(ks * 64 + m)) * N + n];
        s.x += p.x; s.y += p.y; s.z += p.z; s.w += p.w;
    }
    if (res) {
        float4 r = *(const float4*)&res[idx];
        s.x += r.x; s.y += r.y; s.z += r.z; s.w += r.w;
    }
    *(float4*)&C[idx] = s;
}

// ---------------- split-S GQA flash-decode: butterfly-transpose reduce ----------
__global__ __launch_bounds__(256) void attn_part_k(
    const float* __restrict__ kc, const float* __restrict__ vc,
    const int* __restrict__ seq_lens)
{
    int c  = blockIdx.x;
    int kv = blockIdx.y;
    int b  = blockIdx.z;
    int tid = threadIdx.x, warp = tid >> 5, lane = tid & 31;
    int sl = seq_lens[b];
    if (sl < 0) sl = 0;
    if (sl > SEQ - 1) sl = SEQ - 1;
    int L  = sl + 1;
    int s0 = c * SCHUNK;
    if (s0 >= L) return;
    int s1 = s0 + SCHUNK; if (s1 > L) s1 = L;
    const float scale = 0.08838834764831845f;

    const float* qbase = g_qkv + b * QKV_N + kv * GQA * HD;
    const float* knew  = g_qkv + b * QKV_N + NH * HD + kv * HD;
    const float* vnew  = g_qkv + b * QKV_N + (NH + NKV) * HD + kv * HD;

    float4 q[GQA];
    #pragma unroll
    for (int h = 0; h < GQA; h++) {
        q[h] = *(const float4*)(qbase + h * HD + lane * 4);
        q[h].x *= scale; q[h].y *= scale; q[h].z *= scale; q[h].w *= scale;
    }

    float m[GQA], l[GQA];
    float4 o[GQA];
    #pragma unroll
    for (int h = 0; h < GQA; h++) {
        m[h] = -INFINITY; l[h] = 0.f; o[h] = make_float4(0.f, 0.f, 0.f, 0.f);
    }

    int sel1 = (lane >> 4) & 1;
    int sel2 = (lane >> 3) & 1;
    int sel3 = (lane >> 2) & 1;

    int s = s0 + warp;
    if (s < s1) {
        const float* kp = (s == sl) ? knew : (kc + ((size_t)(b * SEQ + s) * NKV + kv) * HD);
        const float* vp = (s == sl) ? vnew : (vc + ((size_t)(b * SEQ + s) * NKV + kv) * HD);
        float4 kk = *(const float4*)(kp + lane * 4);
        float4 vv = *(const float4*)(vp + lane * 4);
        for (;;) {
            int sn = s + 8;
            float4 knx, vnx;
            if (sn < s1) {
                const float* kp2 = (sn == sl) ? knew : (kc + ((size_t)(b * SEQ + sn) * NKV + kv) * HD);
                const float* vp2 = (sn == sl) ? vnew : (vc + ((size_t)(b * SEQ + sn) * NKV + kv) * HD);
                knx = *(const float4*)(kp2 + lane * 4);
                vnx = *(const float4*)(vp2 + lane * 4);
            }
            // partial dots for all 8 heads
            float d[GQA];
            #pragma unroll
            for (int h = 0; h < GQA; h++)
                d[h] = q[h].x * kk.x + q[h].y * kk.y + q[h].z * kk.z + q[h].w * kk.w;
            // butterfly-transpose reduce: 8 heads x 32 lanes -> head (lane>>2)&7
            #pragma unroll
            for (int k = 0; k < 4; k++) {
                float keep = sel1 ? d[k + 4] : d[k];
                float send = sel1 ? d[k]     : d[k + 4];
                d[k] = keep + __shfl_xor_sync(0xffffffffu, send, 16);
            }
            #pragma unroll
            for (int k = 0; k < 2; k++) {
                float keep = sel2 ? d[k + 2] : d[k];
                float send = sel2 ? d[k]     : d[k + 2];
                d[k] = keep + __shfl_xor_sync(0xffffffffu, send, 8);
            }
            {
                float keep = sel3 ? d[1] : d[0];
                float send = sel3 ? d[0] : d[1];
                d[0] = keep + __shfl_xor_sync(0xffffffffu, send, 4);
            }
            d[0] += __shfl_xor_sync(0xffffffffu, d[0], 2);
            d[0] += __shfl_xor_sync(0xffffffffu, d[0], 1);
            // broadcast all 8 head scores to every lane
            float sc[GQA];
            #pragma unroll
            for (int h = 0; h < GQA; h++)
                sc[h] = __shfl_sync(0xffffffffu, d[0], h << 2);
            // online softmax with fast path (warp-uniform branch)
            #pragma unroll
            for (int h = 0; h < GQA; h++) {
                float sv = sc[h];
                if (sv <= m[h]) {
                    float p = __expf(sv - m[h]);
                    l[h] += p;
                    o[h].x = fmaf(p, vv.x, o[h].x);
                    o[h].y = fmaf(p, vv.y, o[h].y);
                    o[h].z = fmaf(p, vv.z, o[h].z);
                    o[h].w = fmaf(p, vv.w, o[h].w);
                } else {
                    float corr = __expf(m[h] - sv);
                    l[h] = fmaf(l[h], corr, 1.f);
                    o[h].x = fmaf(o[h].x, corr, vv.x);
                    o[h].y = fmaf(o[h].y, corr, vv.y);
                    o[h].z = fmaf(o[h].z, corr, vv.z);
                    o[h].w = fmaf(o[h].w, corr, vv.w);
                    m[h] = sv;
                }
            }
            if (sn >= s1) break;
            s = sn; kk = knx; vv = vnx;
        }
    }

    __shared__ float sm[8][GQA], sll[8][GQA];
    __shared__ float so[8][GQA][HD];
    #pragma unroll
    for (int h = 0; h < GQA; h++) {
        if (lane == 0) { sm[warp][h] = m[h]; sll[warp][h] = l[h]; }
        *(float4*)&so[warp][h][lane * 4] = o[h];
    }
    __syncthreads();

    int pbase = ((b * NKV + kv) * NCHUNK + c) * GQA;
    for (int idx = tid; idx < GQA * HD; idx += 256) {
        int h = idx >> 7, d = idx & (HD - 1);
        float M = -INFINITY;
        #pragma unroll
        for (int w = 0; w < 8; w++) M = fmaxf(M, sm[w][h]);
        float acc = 0.f, Ls = 0.f;
        #pragma unroll
        for (int w = 0; w < 8; w++) {
            float cw = __expf(sm[w][h] - M);
            acc += cw * so[w][h][d];
            Ls  += cw * sll[w][h];
        }
        g_po[(pbase + h) * HD + d] = acc;
        if (d == 0) { g_pm[pbase + h] = M; g_pl[pbase + h] = Ls; }
    }
}

// ---------------- combine split-S partials -> bf16 split ----------------
__global__ __launch_bounds__(256) void attn_comb_k(
    const int* __restrict__ seq_lens,
    __nv_bfloat16* __restrict__ outh, __nv_bfloat16* __restrict__ outl)
{
    int b  = blockIdx.x >> 2;
    int kv = blockIdx.x & 3;
    int tid = threadIdx.x;
    int sl = seq_lens[b];
    if (sl < 0) sl = 0;
    if (sl > SEQ - 1) sl = SEQ - 1;
    int nch = sl / SCHUNK + 1;
    int base = (b * NKV + kv) * NCHUNK;

    for (int idx = tid; idx < GQA * HD; idx += 256) {
        int h = idx >> 7, d = idx & (HD - 1);
        float M = -INFINITY;
        for (int c = 0; c < nch; c++) M = fmaxf(M, g_pm[(base + c) * GQA + h]);
        float acc = 0.f, Ls = 0.f;
        for (int c = 0; c < nch; c++) {
            float w = __expf(g_pm[(base + c) * GQA + h] - M);
            acc += w * g_po[((base + c) * GQA + h) * HD + d];
            Ls  += w * g_pl[(base + c) * GQA + h];
        }
        float v = acc / Ls;
        __nv_bfloat16 hh, ll; split1(v, hh, ll);
        long o = (long)b * NH * HD + (kv * GQA + h) * HD + d;
        outh[o] = hh; outl[o] = ll;
    }
}

// ---------------- gate ----------------
__global__ __launch_bounds__(256) void gate_k(const float* __restrict__ gw)
{
    int b = blockIdx.x, tid = threadIdx.x, warp = tid >> 5, lane = tid & 31;
    __shared__ float lg[NEXP];
    const float* h = g_h2 + b * HDIM;
    for (int e = warp; e < NEXP; e += 8) {
        const float* g = gw + e * HDIM;
        float s = 0.f;
        for (int i = lane; i < HDIM; i += 32) s += h[i] * g[i];
        for (int o = 16; o; o >>= 1) s += __shfl_xor_sync(0xffffffffu, s, o);
        if (lane == 0) lg[e] = s;
    }
    __syncthreads();
    if (tid == 0) {
        float val[TOPK]; int idx[TOPK];
        unsigned used = 0;
        for (int j = 0; j < TOPK; j++) {
            float best = -1e30f; int bi = 0;
            for (int e = 0; e < NEXP; e++)
                if (!((used >> e) & 1u) && lg[e] > best) { best = lg[e]; bi = e; }
            used |= 1u << bi; val[j] = best; idx[j] = bi;
        }
        float s = 0.f, wj[TOPK];
        for (int j = 0; j < TOPK; j++) { wj[j] = expf(val[j] - val[0]); s += wj[j]; }
        float is = 1.f / s;
        for (int j = 0; j < TOPK; j++) {
            int e = idx[j];
            int pos = atomicAdd(&g_cnt[e], 1);
            g_tok [e * BATCH + pos] = b;
            g_slot[e * BATCH + pos] = j;
            g_wt  [e * BATCH + pos] = wj[j] * is;
        }
    }
}

// ---------------- MoE w1 (tensor, bf16x3, fused SwiGLU) ----------------
__global__ __launch_bounds__(256) void moe_w1_tc(const float* __restrict__ w1)
{
    int e = blockIdx.y;
    int cnt = g_cnt[e];
    int m0 = blockIdx.z * 16;
    if (m0 >= cnt) return;
    int ib = blockIdx.x * 64;

    __shared__ __align__(16) char SM[46080];
    __nv_bfloat16* pAh = (__nv_bfloat16*)SM;
    __nv_bfloat16* pAl = pAh + 1280;
    __nv_bfloat16* pWh = pAl + 1280;
    __nv_bfloat16* pWl = pWh + 10240;
    float* Csm = (float*)SM;
    __shared__ int toks[16];

    int tid = threadIdx.x, lane = tid & 31, warp = tid >> 5;
    int gr = lane >> 2, tc = lane & 3;
    if (tid < 16) toks[tid] = (m0 + tid < cnt) ? g_tok[e * BATCH + m0 + tid]
                                               : g_tok[e * BATCH];
    __syncthreads();

    int ar = tid >> 4, akp = (tid & 15) * 2;
    const __nv_bfloat16* Agh = g_h2h + (long)toks[ar] * HDIM + akp;
    const __nv_bfloat16* Agl = g_h2l + (long)toks[ar] * HDIM + akp;
    int lw = tid >> 1, wk = (tid & 1) * 16;
    long wrow = (long)e * 2 * IDIM + ((lw < 64) ? (ib + lw) : (IDIM + ib + lw - 64));
    const float* Wg = w1 + wrow * HDIM + wk;

    const int tiles = HDIM / 32;
    float acc[2][4] = {};

    unsigned rah[2], ral[2];
    float4 rw[2][4];
    #pragma unroll
    for (int s = 0; s < 2; s++) {
        rah[s] = *(const unsigned*)(Agh + s * 32);
        ral[s] = *(const unsigned*)(Agl + s * 32);
        #pragma unroll
        for (int q = 0; q < 4; q++) rw[s][q] = *(const float4*)(Wg + s * 32 + q * 4);
    }

    for (int t = 0; t < tiles; t += 2) {
        #pragma unroll
        for (int p = 0; p < 2; p++) {
            *(unsigned*)&pAh[p * 640 + ar * 40 + akp] = rah[p];
            *(unsigned*)&pAl[p * 640 + ar * 40 + akp] = ral[p];
            {
                uint4 uh0, uh1, ul0, ul1;
                split2(rw[p][0].x, rw[p][0].y, uh0.x, ul0.x);
                split2(rw[p][0].z, rw[p][0].w, uh0.y, ul0.y);
                split2(rw[p][1].x, rw[p][1].y, uh0.z, ul0.z);
                split2(rw[p][1].z, rw[p][1].w, uh0.w, ul0.w);
                split2(rw[p][2].x, rw[p][2].y, uh1.x, ul1.x);
                split2(rw[p][2].z, rw[p][2].w, uh1.y, ul1.y);
                split2(rw[p][3].x, rw[p][3].y, uh1.z, ul1.z);
                split2(rw[p][3].z, rw[p][3].w, uh1.w, ul1.w);
                long o = p * 5120 + lw * 40 + wk;
                *(uint4*)&pWh[o] = uh0; *(uint4*)&pWh[o + 8] = uh1;
                *(uint4*)&pWl[o] = ul0; *(uint4*)&pWl[o + 8] = ul1;
            }
            if (t + p + 2 < tiles) {
                rah[p] = *(const unsigned*)(Agh + (t + p + 2) * 32);
                ral[p] = *(const unsigned*)(Agl + (t + p + 2) * 32);
                #pragma unroll
                for (int q = 0; q < 4; q++)
                    rw[p][q] = *(const float4*)(Wg + (t + p + 2) * 32 + q * 4);
            }
            __syncthreads();
            #pragma unroll
            for (int k16 = 0; k16 < 2; k16++) {
                int kc = k16 * 16 + tc * 2;
                unsigned ah0 = *(const unsigned*)&pAh[p * 640 + gr * 40 + kc];
                unsigned ah1 = *(const unsigned*)&pAh[p * 640 + (gr + 8) * 40 + kc];
                unsigned ah2 = *(const unsigned*)&pAh[p * 640 + gr * 40 + kc + 8];
                unsigned ah3 = *(const unsigned*)&pAh[p * 640 + (gr + 8) * 40 + kc + 8];
                unsigned al0 = *(const unsigned*)&pAl[p * 640 + gr * 40 + kc];
                unsigned al1 = *(const unsigned*)&pAl[p * 640 + (gr + 8) * 40 + kc];
                unsigned al2 = *(const unsigned*)&pAl[p * 640 + gr * 40 + kc + 8];
                unsigned al3 = *(const unsigned*)&pAl[p * 640 + (gr + 8) * 40 + kc + 8];
                #pragma unroll
                for (int j = 0; j < 2; j++) {
                    int n = warp * 16 + j * 8 + gr;
                    unsigned bh0 = *(const unsigned*)&pWh[p * 5120 + n * 40 + kc];
                    unsigned bh1 = *(const unsigned*)&pWh[p * 5120 + n * 40 + kc + 8];
                    unsigned bl0 = *(const unsigned*)&pWl[p * 5120 + n * 40 + kc];
                    unsigned bl1 = *(const unsigned*)&pWl[p * 5120 + n * 40 + kc + 8];
                    mma16816(acc[j][0], acc[j][1], acc[j][2], acc[j][3],
                             ah0, ah1, ah2, ah3, bh0, bh1);
                    mma16816(acc[j][0], acc[j][1], acc[j][2], acc[j][3],
                             ah0, ah1, ah2, ah3, bl0, bl1);
                    mma16816(acc[j][0], acc[j][1], acc[j][2], acc[j][3],
                             al0, al1, al2, al3, bh0, bh1);
                }
            }
            __syncthreads();
        }
    }

    #pragma unroll
    for (int j = 0; j < 2; j++) {
        int col = warp * 16 + j * 8 + tc * 2;
        Csm[gr * 132 + col] = acc[j][0];
        Csm[gr * 132 + col + 1] = acc[j][1];
        Csm[(gr + 8) * 132 + col] = acc[j][2];
        Csm[(gr + 8) * 132 + col + 1] = acc[j][3];
    }
    __syncthreads();

    #pragma unroll
    for (int it = 0; it < 4; it++) {
        int idx = tid + it * 256;
        int m = idx >> 6, n = idx & 63;
        if (m0 + m < cnt) {
            float gg = Csm[m * 132 + n];
            float uu = Csm[m * 132 + 64 + n];
            float a = gg / (1.f + expf(-gg)) * uu;
            __nv_bfloat16 h, l; split1(a, h, l);
            long o = (long)(e * BATCH + m0 + m) * IDIM + ib + n;
            g_acth[o] = h; g_actl[o] = l;
        }
    }
}

// ---------------- MoE w2 (tensor, bf16x3, weighted scatter) ----------------
__global__ __launch_bounds__(128) void moe_w2_tc(const float* __restrict__ w2)
{
    int e = blockIdx.y;
    int cnt = g_cnt[e];
    int m0 = blockIdx.z * 16;
    if (m0 >= cnt) return;
    int hb = blockIdx.x * 64;

    __shared__ __nv_bfloat16 sAh[2][16][40], sAl[2][16][40];
    __shared__ __nv_bfloat16 sWh[2][64][40], sWl[2][64][40];

    int tid = threadIdx.x, lane = tid & 31, warp = tid >> 5;
    int gr = lane >> 2, tc = lane & 3;

    int ar = tid >> 3, akp = (tid & 7) * 4;
    const __nv_bfloat16* Agh = g_acth + (long)(e * BATCH + m0 + ar) * IDIM + akp;
    const __nv_bfloat16* Agl = g_actl + (long)(e * BATCH + m0 + ar) * IDIM + akp;
    int lw = tid >> 1, wk = (tid & 1) * 16;
    const float* Wg = w2 + ((long)e * HDIM + hb + lw) * IDIM + wk;

    const int tiles = IDIM / 32;
    float acc[2][4] = {};

    uint2 rah[2], ral[2];
    float4 rw[2][4];
    #pragma unroll
    for (int s = 0; s < 2; s++) {
        rah[s] = *(const uint2*)(Agh + s * 32);
        ral[s] = *(const uint2*)(Agl + s * 32);
        #pragma unroll
        for (int q = 0; q < 4; q++) rw[s][q] = *(const float4*)(Wg + s * 32 + q * 4);
    }

    for (int t = 0; t < tiles; t += 2) {
        #pragma unroll
        for (int p = 0; p < 2; p++) {
            *(uint2*)&sAh[p][ar][akp] = rah[p];
            *(uint2*)&sAl[p][ar][akp] = ral[p];
            {
                uint4 uh0, uh1, ul0, ul1;
                split2(rw[p][0].x, rw[p][0].y, uh0.x, ul0.x);
                split2(rw[p][0].z, rw[p][0].w, uh0.y, ul0.y);
                split2(rw[p][1].x, rw[p][1].y, uh0.z, ul0.z);
                split2(rw[p][1].z, rw[p][1].w, uh0.w, ul0.w);
                split2(rw[p][2].x, rw[p][2].y, uh1.x, ul1.x);
                split2(rw[p][2].z, rw[p][2].w, uh1.y, ul1.y);
                split2(rw[p][3].x, rw[p][3].y, uh1.z, ul1.z);
                split2(rw[p][3].z, rw[p][3].w, uh1.w, ul1.w);
                *(uint4*)&sWh[p][lw][wk] = uh0; *(uint4*)&sWh[p][lw][wk + 8] = uh1;
                *(uint4*)&sWl[p][lw][wk] = ul0; *(uint4*)&sWl[p][lw][wk + 8] = ul1;
            }
            if (t + p + 2 < tiles) {
                rah[p] = *(const uint2*)(Agh + (t + p + 2) * 32);
                ral[p] = *(const uint2*)(Agl + (t + p + 2) * 32);
                #pragma unroll
                for (int q = 0; q < 4; q++)
                    rw[p][q] = *(const float4*)(Wg + (t + p + 2) * 32 + q * 4);
            }
            __syncthreads();
            #pragma unroll
            for (int k16 = 0; k16 < 2; k16++) {
                int kc = k16 * 16 + tc * 2;
                unsigned ah0 = *(const unsigned*)&sAh[p][gr][kc];
                unsigned ah1 = *(const unsigned*)&sAh[p][gr + 8][kc];
                unsigned ah2 = *(const unsigned*)&sAh[p][gr][kc + 8];
                unsigned ah3 = *(const unsigned*)&sAh[p][gr + 8][kc + 8];
                unsigned al0 = *(const unsigned*)&sAl[p][gr][kc];
                unsigned al1 = *(const unsigned*)&sAl[p][gr + 8][kc];
                unsigned al2 = *(const unsigned*)&sAl[p][gr][kc + 8];
                unsigned al3 = *(const unsigned*)&sAl[p][gr + 8][kc + 8];
                #pragma unroll
                for (int j = 0; j < 2; j++) {
                    int n = warp * 16 + j * 8 + gr;
                    unsigned bh0 = *(const unsigned*)&sWh[p][n][kc];
                    unsigned bh1 = *(const unsigned*)&sWh[p][n][kc + 8];
                    unsigned bl0 = *(const unsigned*)&sWl[p][n][kc];
                    unsigned bl1 = *(const unsigned*)&sWl[p][n][kc + 8];
                    mma16816(acc[j][0], acc[j][1], acc[j][2], acc[j][3],
                             ah0, ah1, ah2, ah3, bh0, bh1);
                    mma16816(acc[j][0], acc[j][1], acc[j][2], acc[j][3],
                             ah0, ah1, ah2, ah3, bl0, bl1);
                    mma16816(acc[j][0], acc[j][1], acc[j][2], acc[j][3],
                             al0, al1, al2, al3, bh0, bh1);
                }
            }
            __syncthreads();
        }
    }

    #pragma unroll
    for (int j = 0; j < 2; j++) {
        int col = hb + warp * 16 + j * 8 + tc * 2;
        int m1 = m0 + gr, m2 = m0 + gr + 8;
        if (m1 < cnt) {
            int tok = g_tok[e * BATCH + m1], sj = g_slot[e * BATCH + m1];
            float w = g_wt[e * BATCH + m1];
            float* yp = &g_ypair[(long)(tok * TOPK + sj) * HDIM + col];
            yp[0] = w * acc[j][0]; yp[1] = w * acc[j][1];
        }
        if (m2 < cnt) {
            int tok = g_tok[e * BATCH + m2], sj = g_slot[e * BATCH + m2];
            float w = g_wt[e * BATCH + m2];
            float* yp = &g_ypair[(long)(tok * TOPK + sj) * HDIM + col];
            yp[0] = w * acc[j][2]; yp[1] = w * acc[j][3];
        }
    }
}

// ---------------- finalize ----------------
__global__ __launch_bounds__(256) void finalize_k(float* __restrict__ out)
{
    int idx = blockIdx.x * 256 + threadIdx.x;
    int tok = idx >> 11, hh = idx & (HDIM - 1);
    float s = g_hs2[idx];
    #pragma unroll
    for (int j = 0; j < TOPK; j++) s += g_ypair[(tok * TOPK + j) * HDIM + hh];
    out[idx] = s;
}

// ---------------- launch ----------------
extern "C" void kernel_launch(void* const* d_in, const int* in_sizes, int n_in,
                              void* d_out, int out_size)
{
    static float *p_hn = 0, *p_qkv = 0, *p_hs2 = 0, *p_h2 = 0, *p_part = 0;
    static __nv_bfloat16 *p_hnh = 0, *p_hnl = 0, *p_ath = 0, *p_atl = 0, *p_h2h = 0, *p_h2l = 0;
    if (!p_hn) {
        cudaGetSymbolAddress((void**)&p_hn,   g_hn);
        cudaGetSymbolAddress((void**)&p_qkv,  g_qkv);
        cudaGetSymbolAddress((void**)&p_hs2,  g_hs2);
        cudaGetSymbolAddress((void**)&p_h2,   g_h2);
        cudaGetSymbolAddress((void**)&p_part, g_part);
        cudaGetSymbolAddress((void**)&p_hnh,  g_hnh);
        cudaGetSymbolAddress((void**)&p_hnl,  g_hnl);
        cudaGetSymbolAddress((void**)&p_ath,  g_ath);
        cudaGetSymbolAddress((void**)&p_atl,  g_atl);
        cudaGetSymbolAddress((void**)&p_h2h,  g_h2h);
        cudaGetSymbolAddress((void**)&p_h2l,  g_h2l);
    }

    const float *hidden = 0, *k_cache = 0, *v_cache = 0, *w_qkv = 0, *b_qkv = 0;
    const float *w_o = 0, *ln1_w = 0, *ln2_w = 0, *gate_w = 0, *w1 = 0, *w2 = 0;
    const int *positions = 0, *seqlens = 0;

    for (int i = 0; i < n_in; i++) {
        long sz = (long)in_sizes[i];
        const void* p = d_in[i];
        if      (sz == (long)BATCH * HDIM)            hidden = (const float*)p;
        else if (sz == (long)BATCH) {
            if (!positions) positions = (const int*)p; else seqlens = (const int*)p;
        }
        else if (sz == (long)BATCH * SEQ * NKV * HD) {
            if (!k_cache) k_cache = (const float*)p; else v_cache = (const float*)p;
        }
        else if (sz == (long)QKV_N * HDIM)            w_qkv  = (const float*)p;
        else if (sz == (long)QKV_N)                   b_qkv  = (const float*)p;
        else if (sz == (long)HDIM * NH * HD)          w_o    = (const float*)p;
        else if (sz == (long)HDIM) {
            if (!ln1_w) ln1_w = (const float*)p; else ln2_w = (const float*)p;
        }
        else if (sz == (long)NEXP * HDIM)             gate_w = (const float*)p;
        else if (sz == (long)NEXP * 2 * IDIM * HDIM)  w1     = (const float*)p;
        else if (sz == (long)NEXP * HDIM * IDIM)      w2     = (const float*)p;
    }
    if (!seqlens && positions) seqlens = positions;
    if (!v_cache) v_cache = k_cache;
    if (!ln2_w)   ln2_w   = ln1_w;

    float* out = (float*)d_out;

    reset_k<<<1, 32>>>();
    rmsnorm_k<<<BATCH, 256>>>(hidden, ln1_w, p_hn, p_hnh, p_hnl);
    gemm_part_tc<<<dim3(QKV_N / 64, 4), 256>>>(p_hnh, p_hnl, w_qkv, p_part, QKV_N, HDIM, 4);
    gemm_reduce_k<<<(64 * QKV_N) / 1024, 256>>>(p_part, b_qkv, nullptr, p_qkv, QKV_N, 4);
    attn_part_k<<<dim3(NCHUNK, NKV, BATCH), 256>>>(k_cache, v_cache, seqlens);
    attn_comb_k<<<BATCH * NKV, 256>>>(seqlens, p_ath, p_atl);
    gemm_part_tc<<<dim3(HDIM / 64, 8), 256>>>(p_ath, p_atl, w_o, p_part, HDIM, NH * HD, 8);
    gemm_reduce_k<<<(64 * HDIM) / 1024, 256>>>(p_part, nullptr, hidden, p_hs2, HDIM, 8);
    rmsnorm_k<<<BATCH, 256>>>(p_hs2, ln2_w, p_h2, p_h2h, p_h2l);
    gate_k<<<BATCH, 256>>>(gate_w);
    moe_w1_tc<<<dim3(IDIM / 64, NEXP, 4), 256>>>(w1);
    moe_w2_tc<<<dim3(HDIM / 64, NEXP, 4), 128>>>(w2);
    finalize_k<<<(BATCH * HDIM) / 256, 256>>>(out);
}